// round 15
// baseline (speedup 1.0000x reference)
#include <cuda_runtime.h>
#include <cuda_bf16.h>
#include <math.h>
#include <stdint.h>

// ---------------- problem constants ----------------
#define CDIM   192
#define IMGHW  224
#define HW     (IMGHW*IMGHW)          // 50176
#define BATCH  4
#define HWC    ((size_t)CDIM*HW)
#define NWIN   3136
#define NTOK   200704                 // NWIN * 64 == BATCH*HW
#define OUT_MAIN ((size_t)BATCH*HWC)  // 38,535,168
#define RECON_DENOM 38535168.0

// fp8 scaling: activations x8, weights x16 -> accumulator /128
#define SCL_A 8.0f
#define SCL_W 16.0f
#define SCL_INV (1.0f / (SCL_A * SCL_W))

// ---------------- scratch (device globals) ----------------
__device__ __align__(16) __nv_bfloat16 g_attnb[(size_t)NTOK*192];
__device__ __align__(16) __nv_bfloat16 g_pb   [(size_t)NTOK*192];  // xT first, then pb
__device__ __align__(16) __nv_bfloat16 g_f1b  [(size_t)NTOK*192];  // conv1x1 out
__device__ __align__(16) uint8_t g_vf8 [(size_t)NTOK*192];         // v * 8, e4m3
__device__ __align__(16) uint8_t g_hf8 [(size_t)NTOK*768];         // h * 8, e4m3
__device__ __align__(16) __nv_bfloat16 g_wt_pre [192*192];
__device__ __align__(16) __nv_bfloat16 g_wt_qkv [576*192];
__device__ __align__(16) uint8_t g_wt_g1f8 [768*192];              // w_g1^T * 16
__device__ __align__(16) uint8_t g_wt_g2f8 [192*768];              // w_g2^T * 16
__device__ __align__(16) __nv_bfloat16 g_wt_proj[192*192];
__device__ __align__(16) __nv_bfloat16 g_wt_rec [192*192];
__device__ double g_lossd[1];

// ---------------- HMMA / FP8 MMA / ldmatrix / cp.async helpers ------------
__device__ __forceinline__ void mma_bf16(float c[4],
    uint32_t a0, uint32_t a1, uint32_t a2, uint32_t a3,
    uint32_t b0, uint32_t b1)
{
    asm volatile(
        "mma.sync.aligned.m16n8k16.row.col.f32.bf16.bf16.f32 "
        "{%0,%1,%2,%3}, {%4,%5,%6,%7}, {%8,%9}, {%0,%1,%2,%3};"
        : "+f"(c[0]), "+f"(c[1]), "+f"(c[2]), "+f"(c[3])
        : "r"(a0), "r"(a1), "r"(a2), "r"(a3), "r"(b0), "r"(b1));
}
__device__ __forceinline__ void mma_fp8(float c[4],
    uint32_t a0, uint32_t a1, uint32_t a2, uint32_t a3,
    uint32_t b0, uint32_t b1)
{
    asm volatile(
        "mma.sync.aligned.m16n8k32.row.col.f32.e4m3.e4m3.f32 "
        "{%0,%1,%2,%3}, {%4,%5,%6,%7}, {%8,%9}, {%0,%1,%2,%3};"
        : "+f"(c[0]), "+f"(c[1]), "+f"(c[2]), "+f"(c[3])
        : "r"(a0), "r"(a1), "r"(a2), "r"(a3), "r"(b0), "r"(b1));
}
__device__ __forceinline__ void ldsm4(uint32_t& r0, uint32_t& r1,
                                      uint32_t& r2, uint32_t& r3,
                                      const __nv_bfloat16* p)
{
    uint32_t a = (uint32_t)__cvta_generic_to_shared(p);
    asm volatile("ldmatrix.sync.aligned.m8n8.x4.shared.b16 {%0,%1,%2,%3}, [%4];"
        : "=r"(r0), "=r"(r1), "=r"(r2), "=r"(r3) : "r"(a));
}
__device__ __forceinline__ void cp_async16(__nv_bfloat16* dst, const void* src)
{
    uint32_t d = (uint32_t)__cvta_generic_to_shared(dst);
    asm volatile("cp.async.cg.shared.global [%0], [%1], 16;" :: "r"(d), "l"(src));
}
#define CP_COMMIT() asm volatile("cp.async.commit_group;" ::: "memory")
#define CP_WAIT1()  asm volatile("cp.async.wait_group 1;" ::: "memory")

__device__ __forceinline__ uint16_t to_e4m3x2(float lo, float hi)
{
    uint16_t r;
    asm("cvt.rn.satfinite.e4m3x2.f32 %0, %1, %2;" : "=h"(r) : "f"(hi), "f"(lo));
    return r;
}

// ---------------- bf16 HMMA GEMM (conv1x1) ----------------
__global__ void __launch_bounds__(256)
hmma_gemm(const __nv_bfloat16* __restrict__ A, int lda,
          const __nv_bfloat16* __restrict__ BT, int K,
          const float* __restrict__ bias,
          __nv_bfloat16* __restrict__ Cb, int ldc)
{
    __shared__ __align__(16) __nv_bfloat16 sA[3][128][40];
    __shared__ __align__(16) __nv_bfloat16 sB[3][96][40];

    const int tid = threadIdx.x;
    const int lane = tid & 31, wid = tid >> 5;
    const int wm = wid & 3, wn = wid >> 2;

    const __nv_bfloat16* Ab = A + (size_t)(blockIdx.y * 128) * lda;
    const __nv_bfloat16* Bb = BT + (size_t)(blockIdx.x * 96) * K;

    float acc[2][6][4] = {};
    const int nk = K >> 5;

    const int lr = tid >> 2, lq = tid & 3;
    #define ISSUE_CHUNK(buf, k0) do {                                         \
        cp_async16(&sA[buf][lr][lq * 8],                                      \
                   Ab + (size_t)lr * lda + (k0) + lq * 8);                    \
        cp_async16(&sA[buf][lr + 64][lq * 8],                                 \
                   Ab + (size_t)(lr + 64) * lda + (k0) + lq * 8);             \
        cp_async16(&sB[buf][lr][lq * 8],                                      \
                   Bb + (size_t)lr * K + (k0) + lq * 8);                      \
        if (tid < 128)                                                        \
            cp_async16(&sB[buf][lr + 64][lq * 8],                             \
                       Bb + (size_t)(lr + 64) * K + (k0) + lq * 8);           \
    } while (0)

    ISSUE_CHUNK(0, 0);
    CP_COMMIT();

    for (int kc = 0; kc < nk; kc++) {
        if (kc + 1 < nk) ISSUE_CHUNK((kc + 1) % 3, (kc + 1) * 32);
        CP_COMMIT();
        CP_WAIT1();
        __syncthreads();
        const int b = kc % 3;

        #pragma unroll
        for (int ks = 0; ks < 2; ks++) {
            const int kb = ks * 16;
            uint32_t af[2][4];
            #pragma unroll
            for (int mi = 0; mi < 2; mi++)
                ldsm4(af[mi][0], af[mi][1], af[mi][2], af[mi][3],
                      &sA[b][wm * 32 + mi * 16 + (lane & 15)]
                           [kb + ((lane >> 4) << 3)]);
            uint32_t bfr[6][2];
            #pragma unroll
            for (int nj = 0; nj < 3; nj++)
                ldsm4(bfr[2*nj][0], bfr[2*nj][1], bfr[2*nj+1][0], bfr[2*nj+1][1],
                      &sB[b][wn * 48 + nj * 16 + (lane & 7) + ((lane >> 4) << 3)]
                           [kb + (((lane >> 3) & 1) << 3)]);
            #pragma unroll
            for (int ni = 0; ni < 6; ni++)
                #pragma unroll
                for (int mi = 0; mi < 2; mi++)
                    mma_bf16(acc[mi][ni], af[mi][0], af[mi][1], af[mi][2],
                             af[mi][3], bfr[ni][0], bfr[ni][1]);
        }
    }
    #undef ISSUE_CHUNK

    #pragma unroll
    for (int mi = 0; mi < 2; mi++) {
        #pragma unroll
        for (int ni = 0; ni < 6; ni++) {
            int r0 = blockIdx.y * 128 + wm * 32 + mi * 16 + (lane >> 2);
            int n0 = blockIdx.x * 96 + wn * 48 + ni * 8 + (lane & 3) * 2;
            float b0 = bias[n0], b1 = bias[n0 + 1];
            #pragma unroll
            for (int h = 0; h < 2; h++) {
                int r = r0 + h * 8;
                float v0 = acc[mi][ni][2 * h] + b0;
                float v1 = acc[mi][ni][2 * h + 1] + b1;
                __nv_bfloat162 h2 = __floats2bfloat162_rn(v0, v1);
                *(uint32_t*)(Cb + (size_t)r * ldc + n0) = *(uint32_t*)&h2;
            }
        }
    }
}

// ---------------- fused qkv GEMM + attention ----------------
#define QA_SMEM ((64*584 + 64*200 + 3*192*40 + 192*72) * 2)   // 174080 B

__global__ void __launch_bounds__(768)
qkv_attn_kernel(const __nv_bfloat16* __restrict__ pb,
                const __nv_bfloat16* __restrict__ wtq,
                const float* __restrict__ bq,
                uint8_t* __restrict__ vf8,
                __nv_bfloat16* __restrict__ attnb)
{
    extern __shared__ __align__(16) __nv_bfloat16 sm[];
    __nv_bfloat16* sq = sm;                 // 64 x 584 (qkv result)
    __nv_bfloat16* sA = sm + 37376;         // 64 x 200 (pb tile)
    __nv_bfloat16* sB = sA + 12800;         // 3 x 192 x 40
    __nv_bfloat16* vt = sB + 23040;         // 192 x 72

    const int tid = threadIdx.x, lane = tid & 31, wid = tid >> 5;
    const int win = blockIdx.x;

    const __nv_bfloat16* Ap = pb + (size_t)win * 64 * 192;
    #pragma unroll
    for (int i = 0; i < 2; i++) {
        int id = tid + i * 768;
        int r = id / 24, q = id % 24;
        *(uint4*)(sA + r * 200 + q * 8) = *(const uint4*)(Ap + (size_t)r * 192 + q * 8);
    }

    const int lr = tid >> 2, lq = tid & 3;
    #define QA_ISSUEB(buf, Bg, k0)                                            \
        cp_async16(sB + (buf) * 7680 + lr * 40 + lq * 8,                      \
                   (Bg) + (size_t)lr * 192 + (k0) + lq * 8)

    const int wm = wid & 3, wn = wid >> 2;

    #pragma unroll 1
    for (int pass = 0; pass < 3; pass++) {
        const __nv_bfloat16* Bg = wtq + (size_t)pass * 192 * 192;
        float acc[4][4] = {};
        QA_ISSUEB(0, Bg, 0);
        CP_COMMIT();
        #pragma unroll 1
        for (int kc = 0; kc < 6; kc++) {
            if (kc < 5) QA_ISSUEB((kc + 1) % 3, Bg, (kc + 1) * 32);
            CP_COMMIT();
            CP_WAIT1();
            __syncthreads();
            const __nv_bfloat16* bbuf = sB + (kc % 3) * 7680;
            #pragma unroll
            for (int ks = 0; ks < 2; ks++) {
                const int kb = ks * 16;
                uint32_t a0, a1, a2, a3;
                ldsm4(a0, a1, a2, a3,
                      sA + (wm * 16 + (lane & 15)) * 200
                         + kc * 32 + kb + ((lane >> 4) << 3));
                uint32_t bfr[4][2];
                #pragma unroll
                for (int nj = 0; nj < 2; nj++)
                    ldsm4(bfr[2*nj][0], bfr[2*nj][1], bfr[2*nj+1][0], bfr[2*nj+1][1],
                          bbuf + (wn * 32 + nj * 16 + (lane & 7) + ((lane >> 4) << 3)) * 40
                               + kb + (((lane >> 3) & 1) << 3));
                #pragma unroll
                for (int ni = 0; ni < 4; ni++)
                    mma_bf16(acc[ni], a0, a1, a2, a3, bfr[ni][0], bfr[ni][1]);
            }
        }
        #pragma unroll
        for (int ni = 0; ni < 4; ni++) {
            int n0 = pass * 192 + wn * 32 + ni * 8 + (lane & 3) * 2;
            float b0 = bq[n0], b1 = bq[n0 + 1];
            #pragma unroll
            for (int h = 0; h < 2; h++) {
                int row = wm * 16 + (lane >> 2) + h * 8;
                float v0 = acc[ni][2 * h] + b0;
                float v1 = acc[ni][2 * h + 1] + b1;
                __nv_bfloat162 h2 = __floats2bfloat162_rn(v0, v1);
                *(uint32_t*)(sq + row * 584 + n0) = *(uint32_t*)&h2;
                if (pass == 2)
                    *(uint16_t*)(vf8 + ((size_t)win * 64 + row) * 192 + (n0 - 384)) =
                        to_e4m3x2(v0 * SCL_A, v1 * SCL_A);
            }
        }
    }
    #undef QA_ISSUEB
    __syncthreads();

    #pragma unroll
    for (int i = 0; i < 16; i++) {
        int id = tid + i * 768;
        int t = id & 63, ch = id >> 6;
        vt[ch * 72 + t] = sq[t * 584 + 384 + ch];
    }
    __syncthreads();

    const int h = wid >> 2, q0 = (wid & 3) * 16;
    const int hc = h * 32;

    float sc[8][4] = {};
    #pragma unroll
    for (int ks = 0; ks < 2; ks++) {
        int kof = ks * 16 + (lane & 3) * 2;
        const __nv_bfloat16* qp = sq + (q0 + (lane >> 2)) * 584 + hc + kof;
        uint32_t a0 = *(const uint32_t*)qp;
        uint32_t a1 = *(const uint32_t*)(qp + 8 * 584);
        uint32_t a2 = *(const uint32_t*)(qp + 8);
        uint32_t a3 = *(const uint32_t*)(qp + 8 * 584 + 8);
        #pragma unroll
        for (int nt = 0; nt < 8; nt++) {
            const __nv_bfloat16* kp =
                sq + (nt * 8 + (lane >> 2)) * 584 + 192 + hc + kof;
            mma_bf16(sc[nt], a0, a1, a2, a3,
                     *(const uint32_t*)kp, *(const uint32_t*)(kp + 8));
        }
    }

    float mlo = -1e30f, mhi = -1e30f;
    #pragma unroll
    for (int nt = 0; nt < 8; nt++) {
        #pragma unroll
        for (int j = 0; j < 4; j++) sc[nt][j] *= 0.17677669529663687f;
        mlo = fmaxf(mlo, fmaxf(sc[nt][0], sc[nt][1]));
        mhi = fmaxf(mhi, fmaxf(sc[nt][2], sc[nt][3]));
    }
    mlo = fmaxf(mlo, __shfl_xor_sync(0xFFFFFFFFu, mlo, 1));
    mlo = fmaxf(mlo, __shfl_xor_sync(0xFFFFFFFFu, mlo, 2));
    mhi = fmaxf(mhi, __shfl_xor_sync(0xFFFFFFFFu, mhi, 1));
    mhi = fmaxf(mhi, __shfl_xor_sync(0xFFFFFFFFu, mhi, 2));
    float slo = 0.f, shi = 0.f;
    #pragma unroll
    for (int nt = 0; nt < 8; nt++) {
        sc[nt][0] = __expf(sc[nt][0] - mlo);
        sc[nt][1] = __expf(sc[nt][1] - mlo);
        sc[nt][2] = __expf(sc[nt][2] - mhi);
        sc[nt][3] = __expf(sc[nt][3] - mhi);
        slo += sc[nt][0] + sc[nt][1];
        shi += sc[nt][2] + sc[nt][3];
    }
    slo += __shfl_xor_sync(0xFFFFFFFFu, slo, 1);
    slo += __shfl_xor_sync(0xFFFFFFFFu, slo, 2);
    shi += __shfl_xor_sync(0xFFFFFFFFu, shi, 1);
    shi += __shfl_xor_sync(0xFFFFFFFFu, shi, 2);
    float ilo = 1.0f / slo, ihi = 1.0f / shi;

    float o[4][4] = {};
    #pragma unroll
    for (int ks = 0; ks < 4; ks++) {
        __nv_bfloat162 p0 = __floats2bfloat162_rn(sc[2*ks][0],   sc[2*ks][1]);
        __nv_bfloat162 p1 = __floats2bfloat162_rn(sc[2*ks][2],   sc[2*ks][3]);
        __nv_bfloat162 p2 = __floats2bfloat162_rn(sc[2*ks+1][0], sc[2*ks+1][1]);
        __nv_bfloat162 p3 = __floats2bfloat162_rn(sc[2*ks+1][2], sc[2*ks+1][3]);
        int kof = ks * 16 + (lane & 3) * 2;
        #pragma unroll
        for (int nt = 0; nt < 4; nt++) {
            const __nv_bfloat16* vp = vt + (hc + nt * 8 + (lane >> 2)) * 72 + kof;
            mma_bf16(o[nt], *(uint32_t*)&p0, *(uint32_t*)&p1,
                     *(uint32_t*)&p2, *(uint32_t*)&p3,
                     *(const uint32_t*)vp, *(const uint32_t*)(vp + 8));
        }
    }

    int rlo = q0 + (lane >> 2), col = (lane & 3) * 2;
    #pragma unroll
    for (int nt = 0; nt < 4; nt++) {
        size_t ci = ((size_t)win * 64 + rlo) * 192 + hc + nt * 8 + col;
        __nv_bfloat162 w0 = __floats2bfloat162_rn(o[nt][0] * ilo, o[nt][1] * ilo);
        *(uint32_t*)(attnb + ci) = *(uint32_t*)&w0;
        __nv_bfloat162 w1 = __floats2bfloat162_rn(o[nt][2] * ihi, o[nt][3] * ihi);
        *(uint32_t*)(attnb + ci + (size_t)8 * 192) = *(uint32_t*)&w1;
    }
}

// ---------------- FP8 GEMM with GELU (g1) ----------------
__global__ void __launch_bounds__(256)
fp8_gemm_gelu(const uint8_t* __restrict__ A, int ldaB,
              const uint8_t* __restrict__ BT, int Kb,
              const float* __restrict__ bias,
              uint8_t* __restrict__ Cf8, int ldcB)
{
    __shared__ __align__(16) __nv_bfloat16 sA[3][128][40];
    __shared__ __align__(16) __nv_bfloat16 sB[3][96][40];

    const int tid = threadIdx.x;
    const int lane = tid & 31, wid = tid >> 5;
    const int wm = wid & 3, wn = wid >> 2;

    const uint8_t* Ab = A + (size_t)(blockIdx.y * 128) * ldaB;
    const uint8_t* Bb = BT + (size_t)(blockIdx.x * 96) * Kb;

    float acc[2][6][4] = {};
    const int nk = Kb >> 6;

    const int lr = tid >> 2, lq = tid & 3;
    #define ISSUE_CHUNK8(buf, k0) do {                                        \
        cp_async16(&sA[buf][lr][lq * 8],                                      \
                   Ab + (size_t)lr * ldaB + (k0) + lq * 16);                  \
        cp_async16(&sA[buf][lr + 64][lq * 8],                                 \
                   Ab + (size_t)(lr + 64) * ldaB + (k0) + lq * 16);           \
        cp_async16(&sB[buf][lr][lq * 8],                                      \
                   Bb + (size_t)lr * Kb + (k0) + lq * 16);                    \
        if (tid < 128)                                                        \
            cp_async16(&sB[buf][lr + 64][lq * 8],                             \
                       Bb + (size_t)(lr + 64) * Kb + (k0) + lq * 16);         \
    } while (0)

    ISSUE_CHUNK8(0, 0);
    CP_COMMIT();

    for (int kc = 0; kc < nk; kc++) {
        if (kc + 1 < nk) ISSUE_CHUNK8((kc + 1) % 3, (kc + 1) * 64);
        CP_COMMIT();
        CP_WAIT1();
        __syncthreads();
        const int b = kc % 3;

        #pragma unroll
        for (int ks = 0; ks < 2; ks++) {
            const int kb = ks * 16;
            uint32_t af[2][4];
            #pragma unroll
            for (int mi = 0; mi < 2; mi++)
                ldsm4(af[mi][0], af[mi][1], af[mi][2], af[mi][3],
                      &sA[b][wm * 32 + mi * 16 + (lane & 15)]
                           [kb + ((lane >> 4) << 3)]);
            uint32_t bfr[6][2];
            #pragma unroll
            for (int nj = 0; nj < 3; nj++)
                ldsm4(bfr[2*nj][0], bfr[2*nj][1], bfr[2*nj+1][0], bfr[2*nj+1][1],
                      &sB[b][wn * 48 + nj * 16 + (lane & 7) + ((lane >> 4) << 3)]
                           [kb + (((lane >> 3) & 1) << 3)]);
            #pragma unroll
            for (int ni = 0; ni < 6; ni++)
                #pragma unroll
                for (int mi = 0; mi < 2; mi++)
                    mma_fp8(acc[mi][ni], af[mi][0], af[mi][1], af[mi][2],
                            af[mi][3], bfr[ni][0], bfr[ni][1]);
        }
    }
    #undef ISSUE_CHUNK8

    #pragma unroll
    for (int mi = 0; mi < 2; mi++) {
        #pragma unroll
        for (int ni = 0; ni < 6; ni++) {
            int r0 = blockIdx.y * 128 + wm * 32 + mi * 16 + (lane >> 2);
            int n0 = blockIdx.x * 96 + wn * 48 + ni * 8 + (lane & 3) * 2;
            float b0 = bias[n0], b1 = bias[n0 + 1];
            #pragma unroll
            for (int h = 0; h < 2; h++) {
                int r = r0 + h * 8;
                float v0 = acc[mi][ni][2 * h] * SCL_INV + b0;
                float v1 = acc[mi][ni][2 * h + 1] * SCL_INV + b1;
                v0 = 0.5f * v0 * (1.0f + erff(v0 * 0.70710678118654752f));
                v1 = 0.5f * v1 * (1.0f + erff(v1 * 0.70710678118654752f));
                *(uint16_t*)(Cf8 + (size_t)r * ldcB + n0) =
                    to_e4m3x2(v0 * SCL_A, v1 * SCL_A);
            }
        }
    }
}

// ---------------- fused tail kernel: TWO windows per block ----------------
// 512 threads, 16 warps (4M x 4N), M = 128 rows = 2 adjacent windows.
__device__ __forceinline__ void tail_frag_mma(
    const __nv_bfloat16* __restrict__ As, int asr, int akb,
    const __nv_bfloat16* __restrict__ Bs, int bkb,
    int wm, int wn, int lane, float acc[2][6][4], bool fp8)
{
    uint32_t af[2][4];
    #pragma unroll
    for (int mi = 0; mi < 2; mi++)
        ldsm4(af[mi][0], af[mi][1], af[mi][2], af[mi][3],
              As + (wm * 32 + mi * 16 + (lane & 15)) * asr
                 + akb + ((lane >> 4) << 3));
    uint32_t bfr[6][2];
    #pragma unroll
    for (int nj = 0; nj < 3; nj++)
        ldsm4(bfr[2*nj][0], bfr[2*nj][1], bfr[2*nj+1][0], bfr[2*nj+1][1],
              Bs + (wn * 48 + nj * 16 + (lane & 7) + ((lane >> 4) << 3)) * 40
                 + bkb + (((lane >> 3) & 1) << 3));
    #pragma unroll
    for (int ni = 0; ni < 6; ni++)
        #pragma unroll
        for (int mi = 0; mi < 2; mi++) {
            if (fp8)
                mma_fp8(acc[mi][ni], af[mi][0], af[mi][1], af[mi][2], af[mi][3],
                        bfr[ni][0], bfr[ni][1]);
            else
                mma_bf16(acc[mi][ni], af[mi][0], af[mi][1], af[mi][2], af[mi][3],
                         bfr[ni][0], bfr[ni][1]);
        }
}

// smem: sA 2*128*40 | sB 2*192*40 | ms 128*200 | fs 128*200  (bf16 units)
#define TAIL_SMEM ((2*128*40 + 2*192*40 + 128*200 + 128*200) * 2)   // 153600 B

__global__ void __launch_bounds__(512)
tail_kernel(const uint8_t* __restrict__ hf8,
            const uint8_t* __restrict__ wg2f8, const float* __restrict__ bg2,
            const __nv_bfloat16* __restrict__ attnb,
            const __nv_bfloat16* __restrict__ wproj, const float* __restrict__ bproj,
            const __nv_bfloat16* __restrict__ wrec, const float* __restrict__ brec,
            const __nv_bfloat16* __restrict__ pb, const float* __restrict__ xin,
            float* __restrict__ out, double* __restrict__ lossAcc)
{
    extern __shared__ __align__(16) __nv_bfloat16 sm[];
    __nv_bfloat16* sA = sm;                     // 2 * 5120 units
    __nv_bfloat16* sB = sm + 10240;             // 2 * 7680 units
    __nv_bfloat16* ms = sm + 10240 + 15360;     // 128 * 200
    __nv_bfloat16* fs = ms + 25600;             // 128 * 200
    __shared__ float red[512];

    const int tid = threadIdx.x;
    const int lane = tid & 31, wid = tid >> 5;
    const int wm = wid & 3, wn = wid >> 2;
    const int wpair = blockIdx.x * 2;           // first window of pair
    const size_t rowbase = (size_t)wpair * 64;  // global token row of tile row 0
    const uint8_t* Ab8 = hf8 + rowbase * 768;

    const int lr = tid >> 2, lq = tid & 3;      // lr 0..127
    #define TK_ISSUEA8(buf, k0)                                               \
        cp_async16(sA + (buf) * 5120 + lr * 40 + lq * 8,                      \
                   Ab8 + (size_t)lr * 768 + (k0) + lq * 16)
    #define TK_ISSUEB8(buf, k0) do {                                          \
        cp_async16(sB + (buf) * 7680 + lr * 40 + lq * 8,                      \
                   wg2f8 + (size_t)lr * 768 + (k0) + lq * 16);                \
        { int r = lr + 128; if (r < 192)                                      \
            cp_async16(sB + (buf) * 7680 + r * 40 + lq * 8,                   \
                       wg2f8 + (size_t)r * 768 + (k0) + lq * 16); }           \
    } while (0)
    #define TK_ISSUEB(buf, Bg, ldb, k0) do {                                  \
        cp_async16(sB + (buf) * 7680 + lr * 40 + lq * 8,                      \
                   (Bg) + (size_t)lr * (ldb) + (k0) + lq * 8);                \
        { int r = lr + 128; if (r < 192)                                      \
            cp_async16(sB + (buf) * 7680 + r * 40 + lq * 8,                   \
                       (Bg) + (size_t)r * (ldb) + (k0) + lq * 8); }           \
    } while (0)

    // ---- stage 1 (FP8): m = (h @ W_g2^T + b_g2) * attn,  12 chunks of 64B
    float acc1[2][6][4] = {};
    TK_ISSUEA8(0, 0);
    TK_ISSUEB8(0, 0);
    CP_COMMIT();
    #pragma unroll 1
    for (int kc = 0; kc < 12; kc++) {
        int b = kc & 1;
        if (kc < 11) { TK_ISSUEA8(b ^ 1, (kc + 1) * 64); TK_ISSUEB8(b ^ 1, (kc + 1) * 64); }
        CP_COMMIT();
        CP_WAIT1();
        __syncthreads();
        #pragma unroll
        for (int ks = 0; ks < 2; ks++)
            tail_frag_mma(sA + b * 5120, 40, ks * 16, sB + b * 7680, ks * 16,
                          wm, wn, lane, acc1, true);
        __syncthreads();
    }
    #pragma unroll
    for (int mi = 0; mi < 2; mi++) {
        #pragma unroll
        for (int ni = 0; ni < 6; ni++) {
            int col = wn * 48 + ni * 8 + (lane & 3) * 2;
            float b0 = bg2[col], b1 = bg2[col + 1];
            #pragma unroll
            for (int h = 0; h < 2; h++) {
                int row = wm * 32 + mi * 16 + (lane >> 2) + h * 8;
                size_t ci = (rowbase + row) * 192 + col;
                __nv_bfloat162 av = *(const __nv_bfloat162*)(attnb + ci);
                float v0 = (acc1[mi][ni][2 * h] * SCL_INV + b0) * __bfloat162float(av.x);
                float v1 = (acc1[mi][ni][2 * h + 1] * SCL_INV + b1) * __bfloat162float(av.y);
                __nv_bfloat162 h2 = __floats2bfloat162_rn(v0, v1);
                *(uint32_t*)(ms + row * 200 + col) = *(uint32_t*)&h2;
            }
        }
    }
    __syncthreads();

    // ---- stage 2 (bf16): fused = ms @ W_proj^T + b_proj,  K = 192 ----
    float acc2[2][6][4] = {};
    TK_ISSUEB(0, wproj, 192, 0);
    CP_COMMIT();
    #pragma unroll 1
    for (int kc = 0; kc < 6; kc++) {
        int b = kc & 1;
        if (kc < 5) TK_ISSUEB(b ^ 1, wproj, 192, (kc + 1) * 32);
        CP_COMMIT();
        CP_WAIT1();
        __syncthreads();
        #pragma unroll
        for (int ks = 0; ks < 2; ks++)
            tail_frag_mma(ms, 200, kc * 32 + ks * 16, sB + b * 7680, ks * 16,
                          wm, wn, lane, acc2, false);
        __syncthreads();
    }
    #pragma unroll
    for (int mi = 0; mi < 2; mi++) {
        #pragma unroll
        for (int ni = 0; ni < 6; ni++) {
            int col = wn * 48 + ni * 8 + (lane & 3) * 2;
            float b0 = bproj[col], b1 = bproj[col + 1];
            #pragma unroll
            for (int h = 0; h < 2; h++) {
                int row = wm * 32 + mi * 16 + (lane >> 2) + h * 8;
                float v0 = acc2[mi][ni][2 * h]     + b0;
                float v1 = acc2[mi][ni][2 * h + 1] + b1;
                __nv_bfloat162 h2 = __floats2bfloat162_rn(v0, v1);
                *(uint32_t*)(fs + row * 200 + col) = *(uint32_t*)&h2;
            }
        }
    }
    __syncthreads();

    // ---- stage 3 (bf16): rec = fs @ W_rec^T + b_rec, L1 loss vs pb ----
    float acc3[2][6][4] = {};
    TK_ISSUEB(0, wrec, 192, 0);
    CP_COMMIT();
    #pragma unroll 1
    for (int kc = 0; kc < 6; kc++) {
        int b = kc & 1;
        if (kc < 5) TK_ISSUEB(b ^ 1, wrec, 192, (kc + 1) * 32);
        CP_COMMIT();
        CP_WAIT1();
        __syncthreads();
        #pragma unroll
        for (int ks = 0; ks < 2; ks++)
            tail_frag_mma(fs, 200, kc * 32 + ks * 16, sB + b * 7680, ks * 16,
                          wm, wn, lane, acc3, false);
        __syncthreads();
    }
    float lsum = 0.f;
    #pragma unroll
    for (int mi = 0; mi < 2; mi++) {
        #pragma unroll
        for (int ni = 0; ni < 6; ni++) {
            int col = wn * 48 + ni * 8 + (lane & 3) * 2;
            float b0 = brec[col], b1 = brec[col + 1];
            #pragma unroll
            for (int h = 0; h < 2; h++) {
                int row = wm * 32 + mi * 16 + (lane >> 2) + h * 8;
                size_t ci = (rowbase + row) * 192 + col;
                __nv_bfloat162 pv = *(const __nv_bfloat162*)(pb + ci);
                lsum += fabsf(acc3[mi][ni][2 * h]     + b0 - __bfloat162float(pv.x));
                lsum += fabsf(acc3[mi][ni][2 * h + 1] + b1 - __bfloat162float(pv.y));
            }
        }
    }
    red[tid] = lsum;
    __syncthreads();
    #pragma unroll
    for (int s = 256; s > 0; s >>= 1) {
        if (tid < s) red[tid] += red[tid + s];
        __syncthreads();
    }
    if (tid == 0) atomicAdd(lossAcc, (double)red[0]);

    // ---- stage 4: window reverse + residual -> NCHW out (both windows) ----
    size_t base[2];
    #pragma unroll
    for (int w1 = 0; w1 < 2; w1++) {
        int win = wpair + w1;
        int bb = win / 784, wr = win % 784;
        int wy = wr / 28, wx = wr % 28;
        base[w1] = (size_t)bb * HWC + (size_t)(wy * 8) * IMGHW + wx * 8;
    }
    for (int idx = tid; idx < 128 * 192; idx += 512) {
        int c = idx >> 7, t = idx & 127;
        int w1 = t >> 6, tt = t & 63;
        int iy = tt >> 3, ix = tt & 7;
        size_t o = base[w1] + (size_t)c * HW + iy * IMGHW + ix;
        out[o] = __bfloat162float(fs[t * 200 + c]) + xin[o];
    }
    #undef TK_ISSUEA8
    #undef TK_ISSUEB8
    #undef TK_ISSUEB
}

// ---------------- x transpose: NCHW fp32 -> NHWC bf16 ----------------
__global__ void __launch_bounds__(256)
transpose_x_kernel(const float* __restrict__ x, __nv_bfloat16* __restrict__ xt)
{
    __shared__ float tile[32][33];
    int s0 = blockIdx.x * 32, c0 = blockIdx.y * 32, b = blockIdx.z;
    int tx = threadIdx.x & 31, ty = threadIdx.x >> 5;
    const float* xp = x + (size_t)b * HWC;
    #pragma unroll
    for (int j = 0; j < 4; j++)
        tile[ty + 8 * j][tx] = xp[(size_t)(c0 + ty + 8 * j) * HW + s0 + tx];
    __syncthreads();
    __nv_bfloat16* op = xt + (size_t)b * HW * CDIM;
    #pragma unroll
    for (int j = 0; j < 4; j++)
        op[(size_t)(s0 + ty + 8 * j) * CDIM + c0 + tx] =
            __float2bfloat16(tile[tx][ty + 8 * j]);
}

// ---------------- tiled depthwise 3x3 + LN + window partition -------------
#define DW_SMEM (100 * 192 * 2)   // 38400 B

__global__ void __launch_bounds__(256)
dwconv_ln_kernel(const __nv_bfloat16* __restrict__ in,
                 const float* __restrict__ w, const float* __restrict__ bias,
                 const float* __restrict__ lng, const float* __restrict__ lnb,
                 __nv_bfloat16* __restrict__ pb)
{
    extern __shared__ __align__(16) __nv_bfloat16 halo[];   // [100][192]
    __shared__ float2 swt[9][96];          // [tap][chpair]
    __shared__ float2 sb2[96], sg2[96], sbt2[96];
    int tid = threadIdx.x, lane = tid & 31, wid = tid >> 5;
    int win = blockIdx.x;
    int b = win / 784, wr = win % 784, wy = wr / 28, wx = wr % 28;

    for (int i = tid; i < 1728; i += 256) {
        int c = i / 9, tap = i % 9;
        ((float*)&swt[tap][c >> 1])[c & 1] = w[i];
    }
    if (tid < 96) {
        sb2[tid]  = make_float2(bias[2*tid], bias[2*tid+1]);
        sg2[tid]  = make_float2(lng[2*tid],  lng[2*tid+1]);
        sbt2[tid] = make_float2(lnb[2*tid],  lnb[2*tid+1]);
    }

    const __nv_bfloat16* ip = in + (size_t)b * HW * CDIM;
    int y0 = wy * 8 - 1, x0 = wx * 8 - 1;
    #pragma unroll
    for (int i = 0; i < 10; i++) {
        int id = tid + i * 256;
        if (id < 2400) {
            int ph = id / 24, q = id % 24;
            int hy = ph / 10, hx = ph % 10;
            int gy = y0 + hy, gx = x0 + hx;
            uint4 v = make_uint4(0u, 0u, 0u, 0u);
            if (gy >= 0 && gy < IMGHW && gx >= 0 && gx < IMGHW)
                v = *(const uint4*)(ip + (size_t)(gy * IMGHW + gx) * CDIM + q * 8);
            *(uint4*)(halo + ph * 192 + q * 8) = v;
        }
    }
    __syncthreads();

    #pragma unroll 1
    for (int pi = 0; pi < 8; pi++) {
        int t = wid * 8 + pi;
        int iy = t >> 3, ix = t & 7;
        const __nv_bfloat162* hp =
            (const __nv_bfloat162*)(halo + (iy * 10 + ix) * 192);
        float2 acc[3];
        float s1 = 0.f, s2 = 0.f;
        #pragma unroll
        for (int j = 0; j < 3; j++) {
            int cp = j * 32 + lane;
            float2 a = sb2[cp];
            #pragma unroll
            for (int tap = 0; tap < 9; tap++) {
                int ky = tap / 3, kx = tap % 3;
                __nv_bfloat162 v = hp[(ky * 10 + kx) * 96 + cp];
                float2 wv = swt[tap][cp];
                a.x = fmaf(__bfloat162float(v.x), wv.x, a.x);
                a.y = fmaf(__bfloat162float(v.y), wv.y, a.y);
            }
            acc[j] = a;
            s1 += a.x + a.y;
            s2 = fmaf(a.x, a.x, fmaf(a.y, a.y, s2));
        }
        #pragma unroll
        for (int o = 16; o > 0; o >>= 1) {
            s1 += __shfl_xor_sync(0xFFFFFFFFu, s1, o);
            s2 += __shfl_xor_sync(0xFFFFFFFFu, s2, o);
        }
        float mu = s1 * (1.0f / 192.0f);
        float var = s2 * (1.0f / 192.0f) - mu * mu;
        float rsd = rsqrtf(var + 1e-6f);
        __nv_bfloat16* op = pb + ((size_t)win * 64 + t) * 192;
        #pragma unroll
        for (int j = 0; j < 3; j++) {
            int cp = j * 32 + lane;
            float2 g = sg2[cp], bt = sbt2[cp];
            float v0 = fmaf((acc[j].x - mu) * rsd, g.x, bt.x);
            float v1 = fmaf((acc[j].y - mu) * rsd, g.y, bt.y);
            __nv_bfloat162 h2 = __floats2bfloat162_rn(v0, v1);
            *(uint32_t*)(op + 2 * cp) = *(uint32_t*)&h2;
        }
    }
}

// ---------------- merged weight prep + loss zero ----------------
__global__ void __launch_bounds__(256)
prep_kernel(const float* __restrict__ w_pre1, __nv_bfloat16* __restrict__ wtpre,
            const float* __restrict__ w_qkv,  __nv_bfloat16* __restrict__ wtq,
            const float* __restrict__ w_g1,   uint8_t* __restrict__ wg1f8,
            const float* __restrict__ w_g2,   uint8_t* __restrict__ wg2f8,
            const float* __restrict__ w_proj, __nv_bfloat16* __restrict__ wtp,
            const float* __restrict__ w_rec,  __nv_bfloat16* __restrict__ wtr,
            double* __restrict__ loss)
{
    int i = blockIdx.x * 256 + threadIdx.x;
    if (i == 0) *loss = 0.0;
    if (i < 36864) {
        wtpre[i] = __float2bfloat16(w_pre1[i]);
        return;
    }
    i -= 36864;
    if (i < 110592) {
        int k = i / 576, n = i % 576;
        wtq[n * 192 + k] = __float2bfloat16(w_qkv[i]);
        return;
    }
    i -= 110592;
    if (i < 147456) {
        int k = i / 768, n = i % 768;
        wg1f8[n * 192 + k] = (uint8_t)(to_e4m3x2(w_g1[i] * SCL_W, 0.f) & 0xFF);
        return;
    }
    i -= 147456;
    if (i < 147456) {
        int k = i / 192, n = i % 192;
        wg2f8[n * 768 + k] = (uint8_t)(to_e4m3x2(w_g2[i] * SCL_W, 0.f) & 0xFF);
        return;
    }
    i -= 147456;
    if (i < 36864) {
        int k = i / 192, n = i % 192;
        wtp[n * 192 + k] = __float2bfloat16(w_proj[i]);
        return;
    }
    i -= 36864;
    {
        int k = i / 192, n = i % 192;
        wtr[n * 192 + k] = __float2bfloat16(w_rec[i]);
    }
}

__global__ void finalize_loss_kernel(const double* l, float* out, size_t pos)
{
    out[pos] = (float)(l[0] * (0.1 / RECON_DENOM));
}

// ---------------- launch ----------------
extern "C" void kernel_launch(void* const* d_in, const int* in_sizes, int n_in,
                              void* d_out, int out_size)
{
    const float* x      = (const float*)d_in[0];
    const float* w_pre1 = (const float*)d_in[1];
    const float* b_pre1 = (const float*)d_in[2];
    const float* w_dw   = (const float*)d_in[3];
    const float* b_dw   = (const float*)d_in[4];
    const float* ln_g   = (const float*)d_in[5];
    const float* ln_b   = (const float*)d_in[6];
    const float* w_qkv  = (const float*)d_in[7];
    const float* b_qkv  = (const float*)d_in[8];
    const float* w_proj = (const float*)d_in[9];
    const float* b_proj = (const float*)d_in[10];
    const float* w_g1   = (const float*)d_in[11];
    const float* b_g1   = (const float*)d_in[12];
    const float* w_g2   = (const float*)d_in[13];
    const float* b_g2   = (const float*)d_in[14];
    const float* w_rec  = (const float*)d_in[15];
    const float* b_rec  = (const float*)d_in[16];
    float* out = (float*)d_out;

    double* loss;
    __nv_bfloat16 *attnb, *pb, *f1b;
    uint8_t *vf8, *hf8, *wg1f8, *wg2f8;
    __nv_bfloat16 *wtpre, *wtq, *wtp, *wtr;
    cudaGetSymbolAddress((void**)&attnb, g_attnb);
    cudaGetSymbolAddress((void**)&pb,    g_pb);
    cudaGetSymbolAddress((void**)&f1b,   g_f1b);
    cudaGetSymbolAddress((void**)&vf8,   g_vf8);
    cudaGetSymbolAddress((void**)&hf8,   g_hf8);
    cudaGetSymbolAddress((void**)&wtpre, g_wt_pre);
    cudaGetSymbolAddress((void**)&wtq,   g_wt_qkv);
    cudaGetSymbolAddress((void**)&wg1f8, g_wt_g1f8);
    cudaGetSymbolAddress((void**)&wg2f8, g_wt_g2f8);
    cudaGetSymbolAddress((void**)&wtp,   g_wt_proj);
    cudaGetSymbolAddress((void**)&wtr,   g_wt_rec);
    cudaGetSymbolAddress((void**)&loss,  g_lossd);

    __nv_bfloat16* xt = pb;     // xT dead before pb written (by dwconv_ln)

    cudaFuncSetAttribute(tail_kernel,
                         cudaFuncAttributeMaxDynamicSharedMemorySize, TAIL_SMEM);
    cudaFuncSetAttribute(qkv_attn_kernel,
                         cudaFuncAttributeMaxDynamicSharedMemorySize, QA_SMEM);
    cudaFuncSetAttribute(dwconv_ln_kernel,
                         cudaFuncAttributeMaxDynamicSharedMemorySize, DW_SMEM);

    // 0) weight prep + loss zero
    prep_kernel<<<2016, 256>>>(w_pre1, wtpre, w_qkv, wtq, w_g1, wg1f8,
                               w_g2, wg2f8, w_proj, wtp, w_rec, wtr, loss);

    // 1) x -> NHWC bf16
    transpose_x_kernel<<<dim3(HW / 32, CDIM / 32, BATCH), 256>>>(x, xt);

    // 2) 1x1 conv as HMMA GEMM
    hmma_gemm<<<dim3(2, NTOK / 128), 256>>>(xt, 192, wtpre, 192, b_pre1, f1b, 192);

    // 3) tiled depthwise 3x3 + LN + window partition -> pb (bf16)
    dwconv_ln_kernel<<<NWIN, 256, DW_SMEM>>>(f1b, w_dw, b_dw, ln_g, ln_b, pb);

    // 4+5) fused qkv GEMM + attention -> attnb, vf8
    qkv_attn_kernel<<<NWIN, 768, QA_SMEM>>>(pb, wtq, b_qkv, vf8, attnb);

    // 6) h = gelu(v @ w_g1 + b_g1)  -- FP8 GEMM
    fp8_gemm_gelu<<<dim3(8, NTOK / 128), 256>>>(
        vf8, 192, wg1f8, 192, b_g1, hf8, 768);

    // 7-10) fused tail: 2 windows per block
    tail_kernel<<<NWIN / 2, 512, TAIL_SMEM>>>(
        hf8, wg2f8, b_g2, attnb, wtp, b_proj, wtr, b_rec, pb, x, out, loss);

    // 11) loss scalar
    if ((size_t)out_size > OUT_MAIN)
        finalize_loss_kernel<<<1, 1>>>(loss, out, (size_t)out_size - 1);
}

// round 16
// speedup vs baseline: 1.0758x; 1.0758x over previous
#include <cuda_runtime.h>
#include <cuda_bf16.h>
#include <math.h>
#include <stdint.h>

// ---------------- problem constants ----------------
#define CDIM   192
#define IMGHW  224
#define HW     (IMGHW*IMGHW)          // 50176
#define BATCH  4
#define HWC    ((size_t)CDIM*HW)
#define NWIN   3136
#define NTOK   200704                 // NWIN * 64 == BATCH*HW
#define OUT_MAIN ((size_t)BATCH*HWC)  // 38,535,168
#define RECON_DENOM 38535168.0

// fp8 scaling
#define SCL_A 8.0f                     // v, h activations
#define SCL_M 64.0f                    // m, fused activations
#define SCL_W 16.0f                    // weights
#define SCL_INV  (1.0f / (SCL_A * SCL_W))   // 1/128
#define SCL_INV2 (1.0f / (SCL_M * SCL_W))   // 1/1024

// ---------------- scratch (device globals) ----------------
__device__ __align__(16) __nv_bfloat16 g_attnb[(size_t)NTOK*192];
__device__ __align__(16) __nv_bfloat16 g_pb   [(size_t)NTOK*192];  // xT first, then pb
__device__ __align__(16) __nv_bfloat16 g_f1b  [(size_t)NTOK*192];  // conv1x1 out
__device__ __align__(16) uint8_t g_vf8 [(size_t)NTOK*192];         // v * 8, e4m3
__device__ __align__(16) uint8_t g_hf8 [(size_t)NTOK*768];         // h * 8, e4m3
__device__ __align__(16) __nv_bfloat16 g_wt_pre [192*192];
__device__ __align__(16) __nv_bfloat16 g_wt_qkv [576*192];
__device__ __align__(16) uint8_t g_wt_g1f8 [768*192];              // w_g1^T * 16
__device__ __align__(16) uint8_t g_wt_g2f8 [192*768];              // w_g2^T * 16
__device__ __align__(16) uint8_t g_wt_pjf8 [192*192];              // w_proj^T * 16
__device__ __align__(16) uint8_t g_wt_rcf8 [192*192];              // w_rec^T * 16
__device__ double g_lossd[1];

// ---------------- HMMA / FP8 MMA / ldmatrix / cp.async helpers ------------
__device__ __forceinline__ void mma_bf16(float c[4],
    uint32_t a0, uint32_t a1, uint32_t a2, uint32_t a3,
    uint32_t b0, uint32_t b1)
{
    asm volatile(
        "mma.sync.aligned.m16n8k16.row.col.f32.bf16.bf16.f32 "
        "{%0,%1,%2,%3}, {%4,%5,%6,%7}, {%8,%9}, {%0,%1,%2,%3};"
        : "+f"(c[0]), "+f"(c[1]), "+f"(c[2]), "+f"(c[3])
        : "r"(a0), "r"(a1), "r"(a2), "r"(a3), "r"(b0), "r"(b1));
}
__device__ __forceinline__ void mma_fp8(float c[4],
    uint32_t a0, uint32_t a1, uint32_t a2, uint32_t a3,
    uint32_t b0, uint32_t b1)
{
    asm volatile(
        "mma.sync.aligned.m16n8k32.row.col.f32.e4m3.e4m3.f32 "
        "{%0,%1,%2,%3}, {%4,%5,%6,%7}, {%8,%9}, {%0,%1,%2,%3};"
        : "+f"(c[0]), "+f"(c[1]), "+f"(c[2]), "+f"(c[3])
        : "r"(a0), "r"(a1), "r"(a2), "r"(a3), "r"(b0), "r"(b1));
}
__device__ __forceinline__ void ldsm4(uint32_t& r0, uint32_t& r1,
                                      uint32_t& r2, uint32_t& r3,
                                      const __nv_bfloat16* p)
{
    uint32_t a = (uint32_t)__cvta_generic_to_shared(p);
    asm volatile("ldmatrix.sync.aligned.m8n8.x4.shared.b16 {%0,%1,%2,%3}, [%4];"
        : "=r"(r0), "=r"(r1), "=r"(r2), "=r"(r3) : "r"(a));
}
__device__ __forceinline__ void cp_async16(__nv_bfloat16* dst, const void* src)
{
    uint32_t d = (uint32_t)__cvta_generic_to_shared(dst);
    asm volatile("cp.async.cg.shared.global [%0], [%1], 16;" :: "r"(d), "l"(src));
}
#define CP_COMMIT() asm volatile("cp.async.commit_group;" ::: "memory")
#define CP_WAIT1()  asm volatile("cp.async.wait_group 1;" ::: "memory")

__device__ __forceinline__ uint16_t to_e4m3x2(float lo, float hi)
{
    uint16_t r;
    asm("cvt.rn.satfinite.e4m3x2.f32 %0, %1, %2;" : "=h"(r) : "f"(hi), "f"(lo));
    return r;
}

// ---------------- bf16 HMMA GEMM (conv1x1) ----------------
__global__ void __launch_bounds__(256)
hmma_gemm(const __nv_bfloat16* __restrict__ A, int lda,
          const __nv_bfloat16* __restrict__ BT, int K,
          const float* __restrict__ bias,
          __nv_bfloat16* __restrict__ Cb, int ldc)
{
    __shared__ __align__(16) __nv_bfloat16 sA[3][128][40];
    __shared__ __align__(16) __nv_bfloat16 sB[3][96][40];

    const int tid = threadIdx.x;
    const int lane = tid & 31, wid = tid >> 5;
    const int wm = wid & 3, wn = wid >> 2;

    const __nv_bfloat16* Ab = A + (size_t)(blockIdx.y * 128) * lda;
    const __nv_bfloat16* Bb = BT + (size_t)(blockIdx.x * 96) * K;

    float acc[2][6][4] = {};
    const int nk = K >> 5;

    const int lr = tid >> 2, lq = tid & 3;
    #define ISSUE_CHUNK(buf, k0) do {                                         \
        cp_async16(&sA[buf][lr][lq * 8],                                      \
                   Ab + (size_t)lr * lda + (k0) + lq * 8);                    \
        cp_async16(&sA[buf][lr + 64][lq * 8],                                 \
                   Ab + (size_t)(lr + 64) * lda + (k0) + lq * 8);             \
        cp_async16(&sB[buf][lr][lq * 8],                                      \
                   Bb + (size_t)lr * K + (k0) + lq * 8);                      \
        if (tid < 128)                                                        \
            cp_async16(&sB[buf][lr + 64][lq * 8],                             \
                       Bb + (size_t)(lr + 64) * K + (k0) + lq * 8);           \
    } while (0)

    ISSUE_CHUNK(0, 0);
    CP_COMMIT();

    for (int kc = 0; kc < nk; kc++) {
        if (kc + 1 < nk) ISSUE_CHUNK((kc + 1) % 3, (kc + 1) * 32);
        CP_COMMIT();
        CP_WAIT1();
        __syncthreads();
        const int b = kc % 3;

        #pragma unroll
        for (int ks = 0; ks < 2; ks++) {
            const int kb = ks * 16;
            uint32_t af[2][4];
            #pragma unroll
            for (int mi = 0; mi < 2; mi++)
                ldsm4(af[mi][0], af[mi][1], af[mi][2], af[mi][3],
                      &sA[b][wm * 32 + mi * 16 + (lane & 15)]
                           [kb + ((lane >> 4) << 3)]);
            uint32_t bfr[6][2];
            #pragma unroll
            for (int nj = 0; nj < 3; nj++)
                ldsm4(bfr[2*nj][0], bfr[2*nj][1], bfr[2*nj+1][0], bfr[2*nj+1][1],
                      &sB[b][wn * 48 + nj * 16 + (lane & 7) + ((lane >> 4) << 3)]
                           [kb + (((lane >> 3) & 1) << 3)]);
            #pragma unroll
            for (int ni = 0; ni < 6; ni++)
                #pragma unroll
                for (int mi = 0; mi < 2; mi++)
                    mma_bf16(acc[mi][ni], af[mi][0], af[mi][1], af[mi][2],
                             af[mi][3], bfr[ni][0], bfr[ni][1]);
        }
    }
    #undef ISSUE_CHUNK

    #pragma unroll
    for (int mi = 0; mi < 2; mi++) {
        #pragma unroll
        for (int ni = 0; ni < 6; ni++) {
            int r0 = blockIdx.y * 128 + wm * 32 + mi * 16 + (lane >> 2);
            int n0 = blockIdx.x * 96 + wn * 48 + ni * 8 + (lane & 3) * 2;
            float b0 = bias[n0], b1 = bias[n0 + 1];
            #pragma unroll
            for (int h = 0; h < 2; h++) {
                int r = r0 + h * 8;
                float v0 = acc[mi][ni][2 * h] + b0;
                float v1 = acc[mi][ni][2 * h + 1] + b1;
                __nv_bfloat162 h2 = __floats2bfloat162_rn(v0, v1);
                *(uint32_t*)(Cb + (size_t)r * ldc + n0) = *(uint32_t*)&h2;
            }
        }
    }
}

// ---------------- fused qkv GEMM + attention ----------------
#define QA_SMEM ((64*584 + 64*200 + 3*192*40 + 192*72) * 2)   // 174080 B

__global__ void __launch_bounds__(768)
qkv_attn_kernel(const __nv_bfloat16* __restrict__ pb,
                const __nv_bfloat16* __restrict__ wtq,
                const float* __restrict__ bq,
                uint8_t* __restrict__ vf8,
                __nv_bfloat16* __restrict__ attnb)
{
    extern __shared__ __align__(16) __nv_bfloat16 sm[];
    __nv_bfloat16* sq = sm;                 // 64 x 584 (qkv result)
    __nv_bfloat16* sA = sm + 37376;         // 64 x 200 (pb tile)
    __nv_bfloat16* sB = sA + 12800;         // 3 x 192 x 40
    __nv_bfloat16* vt = sB + 23040;         // 192 x 72

    const int tid = threadIdx.x, lane = tid & 31, wid = tid >> 5;
    const int win = blockIdx.x;

    const __nv_bfloat16* Ap = pb + (size_t)win * 64 * 192;
    #pragma unroll
    for (int i = 0; i < 2; i++) {
        int id = tid + i * 768;
        int r = id / 24, q = id % 24;
        *(uint4*)(sA + r * 200 + q * 8) = *(const uint4*)(Ap + (size_t)r * 192 + q * 8);
    }

    const int lr = tid >> 2, lq = tid & 3;
    #define QA_ISSUEB(buf, Bg, k0)                                            \
        cp_async16(sB + (buf) * 7680 + lr * 40 + lq * 8,                      \
                   (Bg) + (size_t)lr * 192 + (k0) + lq * 8)

    const int wm = wid & 3, wn = wid >> 2;

    #pragma unroll 1
    for (int pass = 0; pass < 3; pass++) {
        const __nv_bfloat16* Bg = wtq + (size_t)pass * 192 * 192;
        float acc[4][4] = {};
        QA_ISSUEB(0, Bg, 0);
        CP_COMMIT();
        #pragma unroll 1
        for (int kc = 0; kc < 6; kc++) {
            if (kc < 5) QA_ISSUEB((kc + 1) % 3, Bg, (kc + 1) * 32);
            CP_COMMIT();
            CP_WAIT1();
            __syncthreads();
            const __nv_bfloat16* bbuf = sB + (kc % 3) * 7680;
            #pragma unroll
            for (int ks = 0; ks < 2; ks++) {
                const int kb = ks * 16;
                uint32_t a0, a1, a2, a3;
                ldsm4(a0, a1, a2, a3,
                      sA + (wm * 16 + (lane & 15)) * 200
                         + kc * 32 + kb + ((lane >> 4) << 3));
                uint32_t bfr[4][2];
                #pragma unroll
                for (int nj = 0; nj < 2; nj++)
                    ldsm4(bfr[2*nj][0], bfr[2*nj][1], bfr[2*nj+1][0], bfr[2*nj+1][1],
                          bbuf + (wn * 32 + nj * 16 + (lane & 7) + ((lane >> 4) << 3)) * 40
                               + kb + (((lane >> 3) & 1) << 3));
                #pragma unroll
                for (int ni = 0; ni < 4; ni++)
                    mma_bf16(acc[ni], a0, a1, a2, a3, bfr[ni][0], bfr[ni][1]);
            }
        }
        #pragma unroll
        for (int ni = 0; ni < 4; ni++) {
            int n0 = pass * 192 + wn * 32 + ni * 8 + (lane & 3) * 2;
            float b0 = bq[n0], b1 = bq[n0 + 1];
            #pragma unroll
            for (int h = 0; h < 2; h++) {
                int row = wm * 16 + (lane >> 2) + h * 8;
                float v0 = acc[ni][2 * h] + b0;
                float v1 = acc[ni][2 * h + 1] + b1;
                __nv_bfloat162 h2 = __floats2bfloat162_rn(v0, v1);
                *(uint32_t*)(sq + row * 584 + n0) = *(uint32_t*)&h2;
                if (pass == 2)
                    *(uint16_t*)(vf8 + ((size_t)win * 64 + row) * 192 + (n0 - 384)) =
                        to_e4m3x2(v0 * SCL_A, v1 * SCL_A);
            }
        }
    }
    #undef QA_ISSUEB
    __syncthreads();

    #pragma unroll
    for (int i = 0; i < 16; i++) {
        int id = tid + i * 768;
        int t = id & 63, ch = id >> 6;
        vt[ch * 72 + t] = sq[t * 584 + 384 + ch];
    }
    __syncthreads();

    const int h = wid >> 2, q0 = (wid & 3) * 16;
    const int hc = h * 32;

    float sc[8][4] = {};
    #pragma unroll
    for (int ks = 0; ks < 2; ks++) {
        int kof = ks * 16 + (lane & 3) * 2;
        const __nv_bfloat16* qp = sq + (q0 + (lane >> 2)) * 584 + hc + kof;
        uint32_t a0 = *(const uint32_t*)qp;
        uint32_t a1 = *(const uint32_t*)(qp + 8 * 584);
        uint32_t a2 = *(const uint32_t*)(qp + 8);
        uint32_t a3 = *(const uint32_t*)(qp + 8 * 584 + 8);
        #pragma unroll
        for (int nt = 0; nt < 8; nt++) {
            const __nv_bfloat16* kp =
                sq + (nt * 8 + (lane >> 2)) * 584 + 192 + hc + kof;
            mma_bf16(sc[nt], a0, a1, a2, a3,
                     *(const uint32_t*)kp, *(const uint32_t*)(kp + 8));
        }
    }

    float mlo = -1e30f, mhi = -1e30f;
    #pragma unroll
    for (int nt = 0; nt < 8; nt++) {
        #pragma unroll
        for (int j = 0; j < 4; j++) sc[nt][j] *= 0.17677669529663687f;
        mlo = fmaxf(mlo, fmaxf(sc[nt][0], sc[nt][1]));
        mhi = fmaxf(mhi, fmaxf(sc[nt][2], sc[nt][3]));
    }
    mlo = fmaxf(mlo, __shfl_xor_sync(0xFFFFFFFFu, mlo, 1));
    mlo = fmaxf(mlo, __shfl_xor_sync(0xFFFFFFFFu, mlo, 2));
    mhi = fmaxf(mhi, __shfl_xor_sync(0xFFFFFFFFu, mhi, 1));
    mhi = fmaxf(mhi, __shfl_xor_sync(0xFFFFFFFFu, mhi, 2));
    float slo = 0.f, shi = 0.f;
    #pragma unroll
    for (int nt = 0; nt < 8; nt++) {
        sc[nt][0] = __expf(sc[nt][0] - mlo);
        sc[nt][1] = __expf(sc[nt][1] - mlo);
        sc[nt][2] = __expf(sc[nt][2] - mhi);
        sc[nt][3] = __expf(sc[nt][3] - mhi);
        slo += sc[nt][0] + sc[nt][1];
        shi += sc[nt][2] + sc[nt][3];
    }
    slo += __shfl_xor_sync(0xFFFFFFFFu, slo, 1);
    slo += __shfl_xor_sync(0xFFFFFFFFu, slo, 2);
    shi += __shfl_xor_sync(0xFFFFFFFFu, shi, 1);
    shi += __shfl_xor_sync(0xFFFFFFFFu, shi, 2);
    float ilo = 1.0f / slo, ihi = 1.0f / shi;

    float o[4][4] = {};
    #pragma unroll
    for (int ks = 0; ks < 4; ks++) {
        __nv_bfloat162 p0 = __floats2bfloat162_rn(sc[2*ks][0],   sc[2*ks][1]);
        __nv_bfloat162 p1 = __floats2bfloat162_rn(sc[2*ks][2],   sc[2*ks][3]);
        __nv_bfloat162 p2 = __floats2bfloat162_rn(sc[2*ks+1][0], sc[2*ks+1][1]);
        __nv_bfloat162 p3 = __floats2bfloat162_rn(sc[2*ks+1][2], sc[2*ks+1][3]);
        int kof = ks * 16 + (lane & 3) * 2;
        #pragma unroll
        for (int nt = 0; nt < 4; nt++) {
            const __nv_bfloat16* vp = vt + (hc + nt * 8 + (lane >> 2)) * 72 + kof;
            mma_bf16(o[nt], *(uint32_t*)&p0, *(uint32_t*)&p1,
                     *(uint32_t*)&p2, *(uint32_t*)&p3,
                     *(const uint32_t*)vp, *(const uint32_t*)(vp + 8));
        }
    }

    int rlo = q0 + (lane >> 2), col = (lane & 3) * 2;
    #pragma unroll
    for (int nt = 0; nt < 4; nt++) {
        size_t ci = ((size_t)win * 64 + rlo) * 192 + hc + nt * 8 + col;
        __nv_bfloat162 w0 = __floats2bfloat162_rn(o[nt][0] * ilo, o[nt][1] * ilo);
        *(uint32_t*)(attnb + ci) = *(uint32_t*)&w0;
        __nv_bfloat162 w1 = __floats2bfloat162_rn(o[nt][2] * ihi, o[nt][3] * ihi);
        *(uint32_t*)(attnb + ci + (size_t)8 * 192) = *(uint32_t*)&w1;
    }
}

// ---------------- FP8 GEMM with GELU (g1) ----------------
__global__ void __launch_bounds__(256)
fp8_gemm_gelu(const uint8_t* __restrict__ A, int ldaB,
              const uint8_t* __restrict__ BT, int Kb,
              const float* __restrict__ bias,
              uint8_t* __restrict__ Cf8, int ldcB)
{
    __shared__ __align__(16) __nv_bfloat16 sA[3][128][40];
    __shared__ __align__(16) __nv_bfloat16 sB[3][96][40];

    const int tid = threadIdx.x;
    const int lane = tid & 31, wid = tid >> 5;
    const int wm = wid & 3, wn = wid >> 2;

    const uint8_t* Ab = A + (size_t)(blockIdx.y * 128) * ldaB;
    const uint8_t* Bb = BT + (size_t)(blockIdx.x * 96) * Kb;

    float acc[2][6][4] = {};
    const int nk = Kb >> 6;

    const int lr = tid >> 2, lq = tid & 3;
    #define ISSUE_CHUNK8(buf, k0) do {                                        \
        cp_async16(&sA[buf][lr][lq * 8],                                      \
                   Ab + (size_t)lr * ldaB + (k0) + lq * 16);                  \
        cp_async16(&sA[buf][lr + 64][lq * 8],                                 \
                   Ab + (size_t)(lr + 64) * ldaB + (k0) + lq * 16);           \
        cp_async16(&sB[buf][lr][lq * 8],                                      \
                   Bb + (size_t)lr * Kb + (k0) + lq * 16);                    \
        if (tid < 128)                                                        \
            cp_async16(&sB[buf][lr + 64][lq * 8],                             \
                       Bb + (size_t)(lr + 64) * Kb + (k0) + lq * 16);         \
    } while (0)

    ISSUE_CHUNK8(0, 0);
    CP_COMMIT();

    for (int kc = 0; kc < nk; kc++) {
        if (kc + 1 < nk) ISSUE_CHUNK8((kc + 1) % 3, (kc + 1) * 64);
        CP_COMMIT();
        CP_WAIT1();
        __syncthreads();
        const int b = kc % 3;

        #pragma unroll
        for (int ks = 0; ks < 2; ks++) {
            const int kb = ks * 16;
            uint32_t af[2][4];
            #pragma unroll
            for (int mi = 0; mi < 2; mi++)
                ldsm4(af[mi][0], af[mi][1], af[mi][2], af[mi][3],
                      &sA[b][wm * 32 + mi * 16 + (lane & 15)]
                           [kb + ((lane >> 4) << 3)]);
            uint32_t bfr[6][2];
            #pragma unroll
            for (int nj = 0; nj < 3; nj++)
                ldsm4(bfr[2*nj][0], bfr[2*nj][1], bfr[2*nj+1][0], bfr[2*nj+1][1],
                      &sB[b][wn * 48 + nj * 16 + (lane & 7) + ((lane >> 4) << 3)]
                           [kb + (((lane >> 3) & 1) << 3)]);
            #pragma unroll
            for (int ni = 0; ni < 6; ni++)
                #pragma unroll
                for (int mi = 0; mi < 2; mi++)
                    mma_fp8(acc[mi][ni], af[mi][0], af[mi][1], af[mi][2],
                            af[mi][3], bfr[ni][0], bfr[ni][1]);
        }
    }
    #undef ISSUE_CHUNK8

    #pragma unroll
    for (int mi = 0; mi < 2; mi++) {
        #pragma unroll
        for (int ni = 0; ni < 6; ni++) {
            int r0 = blockIdx.y * 128 + wm * 32 + mi * 16 + (lane >> 2);
            int n0 = blockIdx.x * 96 + wn * 48 + ni * 8 + (lane & 3) * 2;
            float b0 = bias[n0], b1 = bias[n0 + 1];
            #pragma unroll
            for (int h = 0; h < 2; h++) {
                int r = r0 + h * 8;
                float v0 = acc[mi][ni][2 * h] * SCL_INV + b0;
                float v1 = acc[mi][ni][2 * h + 1] * SCL_INV + b1;
                v0 = 0.5f * v0 * (1.0f + erff(v0 * 0.70710678118654752f));
                v1 = 0.5f * v1 * (1.0f + erff(v1 * 0.70710678118654752f));
                *(uint16_t*)(Cf8 + (size_t)r * ldcB + n0) =
                    to_e4m3x2(v0 * SCL_A, v1 * SCL_A);
            }
        }
    }
}

// ---------------- fused tail kernel (R14 shape; fp8 proj/rec) -------------
// One block per window (64 tokens). 256 threads, warps 2(M) x 4(N).
__device__ __forceinline__ void tail_frag_mma(
    const __nv_bfloat16* __restrict__ As, int asr, int akb,
    const __nv_bfloat16* __restrict__ Bs, int bkb,
    int wm, int wn, int lane, float acc[2][6][4], bool fp8)
{
    uint32_t af[2][4];
    #pragma unroll
    for (int mi = 0; mi < 2; mi++)
        ldsm4(af[mi][0], af[mi][1], af[mi][2], af[mi][3],
              As + (wm * 32 + mi * 16 + (lane & 15)) * asr
                 + akb + ((lane >> 4) << 3));
    uint32_t bfr[6][2];
    #pragma unroll
    for (int nj = 0; nj < 3; nj++)
        ldsm4(bfr[2*nj][0], bfr[2*nj][1], bfr[2*nj+1][0], bfr[2*nj+1][1],
              Bs + (wn * 48 + nj * 16 + (lane & 7) + ((lane >> 4) << 3)) * 40
                 + bkb + (((lane >> 3) & 1) << 3));
    #pragma unroll
    for (int ni = 0; ni < 6; ni++)
        #pragma unroll
        for (int mi = 0; mi < 2; mi++) {
            if (fp8)
                mma_fp8(acc[mi][ni], af[mi][0], af[mi][1], af[mi][2], af[mi][3],
                        bfr[ni][0], bfr[ni][1]);
            else
                mma_bf16(acc[mi][ni], af[mi][0], af[mi][1], af[mi][2], af[mi][3],
                         bfr[ni][0], bfr[ni][1]);
        }
}

// smem: sA 2*64*40u | sB 2*192*40u | ms8 64*208B | fs 64*200u | fs8 64*208B
#define TAIL_SMEM (10240 + 30720 + 13312 + 25600 + 13312)   // 93184 B

__global__ void __launch_bounds__(256)
tail_kernel(const uint8_t* __restrict__ hf8,
            const uint8_t* __restrict__ wg2f8, const float* __restrict__ bg2,
            const __nv_bfloat16* __restrict__ attnb,
            const uint8_t* __restrict__ wpjf8, const float* __restrict__ bproj,
            const uint8_t* __restrict__ wrcf8, const float* __restrict__ brec,
            const __nv_bfloat16* __restrict__ pb, const float* __restrict__ xin,
            float* __restrict__ out, double* __restrict__ lossAcc)
{
    extern __shared__ __align__(16) __nv_bfloat16 sm[];
    __nv_bfloat16* sA  = sm;                   // 2 * 2560 units
    __nv_bfloat16* sB  = sm + 5120;            // 2 * 7680 units
    uint8_t* ms8 = (uint8_t*)(sm + 20480);     // 64 x 208 B
    __nv_bfloat16* fs  = sm + 27136;           // 64 x 200 units
    uint8_t* fs8 = (uint8_t*)(sm + 39936);     // 64 x 208 B
    __shared__ float red[256];

    const int tid = threadIdx.x;
    const int lane = tid & 31, wid = tid >> 5;
    const int wm = wid & 1, wn = wid >> 1;
    const int win = blockIdx.x;
    const uint8_t* Ab8 = hf8 + (size_t)win * 64 * 768;

    const int lr = tid >> 2, lq = tid & 3;
    #define TK_ISSUEA8(buf, k0)                                               \
        cp_async16(sA + (buf) * 2560 + lr * 40 + lq * 8,                      \
                   Ab8 + (size_t)lr * 768 + (k0) + lq * 16)
    #define TK_ISSUEB8(buf, Bg, ldb, k0) do {                                 \
        _Pragma("unroll")                                                     \
        for (int i = 0; i < 3; i++) {                                         \
            int r = lr + i * 64;                                              \
            cp_async16(sB + (buf) * 7680 + r * 40 + lq * 8,                   \
                       (Bg) + (size_t)r * (ldb) + (k0) + lq * 16);            \
        }                                                                     \
    } while (0)

    // ---- stage 1 (FP8): m = (h @ W_g2^T + b_g2) * attn, 12 chunks of 64B
    float acc1[2][6][4] = {};
    TK_ISSUEA8(0, 0);
    TK_ISSUEB8(0, wg2f8, 768, 0);
    CP_COMMIT();
    #pragma unroll 1
    for (int kc = 0; kc < 12; kc++) {
        int b = kc & 1;
        if (kc < 11) { TK_ISSUEA8(b ^ 1, (kc + 1) * 64); TK_ISSUEB8(b ^ 1, wg2f8, 768, (kc + 1) * 64); }
        CP_COMMIT();
        CP_WAIT1();
        __syncthreads();
        #pragma unroll
        for (int ks = 0; ks < 2; ks++)
            tail_frag_mma(sA + b * 2560, 40, ks * 16, sB + b * 7680, ks * 16,
                          wm, wn, lane, acc1, true);
        __syncthreads();
    }
    #pragma unroll
    for (int mi = 0; mi < 2; mi++) {
        #pragma unroll
        for (int ni = 0; ni < 6; ni++) {
            int col = wn * 48 + ni * 8 + (lane & 3) * 2;
            float b0 = bg2[col], b1 = bg2[col + 1];
            #pragma unroll
            for (int h = 0; h < 2; h++) {
                int row = wm * 32 + mi * 16 + (lane >> 2) + h * 8;
                size_t ci = ((size_t)win * 64 + row) * 192 + col;
                __nv_bfloat162 av = *(const __nv_bfloat162*)(attnb + ci);
                float v0 = (acc1[mi][ni][2 * h] * SCL_INV + b0) * __bfloat162float(av.x);
                float v1 = (acc1[mi][ni][2 * h + 1] * SCL_INV + b1) * __bfloat162float(av.y);
                *(uint16_t*)(ms8 + row * 208 + col) =
                    to_e4m3x2(v0 * SCL_M, v1 * SCL_M);
            }
        }
    }
    __syncthreads();

    // ---- stage 2 (FP8): fused = m @ W_proj^T + b_proj, 3 chunks of 64B ----
    float acc2[2][6][4] = {};
    TK_ISSUEB8(0, wpjf8, 192, 0);
    CP_COMMIT();
    #pragma unroll 1
    for (int kc = 0; kc < 3; kc++) {
        int b = kc & 1;
        if (kc < 2) TK_ISSUEB8(b ^ 1, wpjf8, 192, (kc + 1) * 64);
        CP_COMMIT();
        CP_WAIT1();
        __syncthreads();
        #pragma unroll
        for (int ks = 0; ks < 2; ks++)
            tail_frag_mma((const __nv_bfloat16*)ms8, 104, kc * 32 + ks * 16,
                          sB + b * 7680, ks * 16, wm, wn, lane, acc2, true);
        __syncthreads();
    }
    #pragma unroll
    for (int mi = 0; mi < 2; mi++) {
        #pragma unroll
        for (int ni = 0; ni < 6; ni++) {
            int col = wn * 48 + ni * 8 + (lane & 3) * 2;
            float b0 = bproj[col], b1 = bproj[col + 1];
            #pragma unroll
            for (int h = 0; h < 2; h++) {
                int row = wm * 32 + mi * 16 + (lane >> 2) + h * 8;
                float v0 = acc2[mi][ni][2 * h]     * SCL_INV2 + b0;
                float v1 = acc2[mi][ni][2 * h + 1] * SCL_INV2 + b1;
                __nv_bfloat162 h2 = __floats2bfloat162_rn(v0, v1);
                *(uint32_t*)(fs + row * 200 + col) = *(uint32_t*)&h2;
                *(uint16_t*)(fs8 + row * 208 + col) =
                    to_e4m3x2(v0 * SCL_M, v1 * SCL_M);
            }
        }
    }
    __syncthreads();

    // ---- stage 3 (FP8): rec = fused @ W_rec^T + b_rec, L1 loss vs pb -----
    float acc3[2][6][4] = {};
    TK_ISSUEB8(0, wrcf8, 192, 0);
    CP_COMMIT();
    #pragma unroll 1
    for (int kc = 0; kc < 3; kc++) {
        int b = kc & 1;
        if (kc < 2) TK_ISSUEB8(b ^ 1, wrcf8, 192, (kc + 1) * 64);
        CP_COMMIT();
        CP_WAIT1();
        __syncthreads();
        #pragma unroll
        for (int ks = 0; ks < 2; ks++)
            tail_frag_mma((const __nv_bfloat16*)fs8, 104, kc * 32 + ks * 16,
                          sB + b * 7680, ks * 16, wm, wn, lane, acc3, true);
        __syncthreads();
    }
    float lsum = 0.f;
    #pragma unroll
    for (int mi = 0; mi < 2; mi++) {
        #pragma unroll
        for (int ni = 0; ni < 6; ni++) {
            int col = wn * 48 + ni * 8 + (lane & 3) * 2;
            float b0 = brec[col], b1 = brec[col + 1];
            #pragma unroll
            for (int h = 0; h < 2; h++) {
                int row = wm * 32 + mi * 16 + (lane >> 2) + h * 8;
                size_t ci = ((size_t)win * 64 + row) * 192 + col;
                __nv_bfloat162 pv = *(const __nv_bfloat162*)(pb + ci);
                lsum += fabsf(acc3[mi][ni][2 * h]     * SCL_INV2 + b0 - __bfloat162float(pv.x));
                lsum += fabsf(acc3[mi][ni][2 * h + 1] * SCL_INV2 + b1 - __bfloat162float(pv.y));
            }
        }
    }
    red[tid] = lsum;
    __syncthreads();
    #pragma unroll
    for (int s = 128; s > 0; s >>= 1) {
        if (tid < s) red[tid] += red[tid + s];
        __syncthreads();
    }
    if (tid == 0) atomicAdd(lossAcc, (double)red[0]);

    // ---- stage 4: window reverse + residual -> NCHW out ----
    int bb = win / 784;
    int wr = win % 784;
    int wy = wr / 28, wx = wr % 28;
    size_t base = (size_t)bb * HWC + (size_t)(wy * 8) * IMGHW + wx * 8;
    for (int idx = tid; idx < 64 * 192; idx += 256) {
        int c = idx >> 6, t = idx & 63;
        int iy = t >> 3, ix = t & 7;
        size_t o = base + (size_t)c * HW + iy * IMGHW + ix;
        out[o] = __bfloat162float(fs[t * 200 + c]) + xin[o];
    }
    #undef TK_ISSUEA8
    #undef TK_ISSUEB8
}

// ---------------- x transpose: NCHW fp32 -> NHWC bf16 ----------------
__global__ void __launch_bounds__(256)
transpose_x_kernel(const float* __restrict__ x, __nv_bfloat16* __restrict__ xt)
{
    __shared__ float tile[32][33];
    int s0 = blockIdx.x * 32, c0 = blockIdx.y * 32, b = blockIdx.z;
    int tx = threadIdx.x & 31, ty = threadIdx.x >> 5;
    const float* xp = x + (size_t)b * HWC;
    #pragma unroll
    for (int j = 0; j < 4; j++)
        tile[ty + 8 * j][tx] = xp[(size_t)(c0 + ty + 8 * j) * HW + s0 + tx];
    __syncthreads();
    __nv_bfloat16* op = xt + (size_t)b * HW * CDIM;
    #pragma unroll
    for (int j = 0; j < 4; j++)
        op[(size_t)(s0 + ty + 8 * j) * CDIM + c0 + tx] =
            __float2bfloat16(tile[tx][ty + 8 * j]);
}

// ---------------- tiled depthwise 3x3 + LN + window partition -------------
#define DW_SMEM (100 * 192 * 2)   // 38400 B

__global__ void __launch_bounds__(256)
dwconv_ln_kernel(const __nv_bfloat16* __restrict__ in,
                 const float* __restrict__ w, const float* __restrict__ bias,
                 const float* __restrict__ lng, const float* __restrict__ lnb,
                 __nv_bfloat16* __restrict__ pb)
{
    extern __shared__ __align__(16) __nv_bfloat16 halo[];   // [100][192]
    __shared__ float2 swt[9][96];          // [tap][chpair]
    __shared__ float2 sb2[96], sg2[96], sbt2[96];
    int tid = threadIdx.x, lane = tid & 31, wid = tid >> 5;
    int win = blockIdx.x;
    int b = win / 784, wr = win % 784, wy = wr / 28, wx = wr % 28;

    for (int i = tid; i < 1728; i += 256) {
        int c = i / 9, tap = i % 9;
        ((float*)&swt[tap][c >> 1])[c & 1] = w[i];
    }
    if (tid < 96) {
        sb2[tid]  = make_float2(bias[2*tid], bias[2*tid+1]);
        sg2[tid]  = make_float2(lng[2*tid],  lng[2*tid+1]);
        sbt2[tid] = make_float2(lnb[2*tid],  lnb[2*tid+1]);
    }

    const __nv_bfloat16* ip = in + (size_t)b * HW * CDIM;
    int y0 = wy * 8 - 1, x0 = wx * 8 - 1;
    #pragma unroll
    for (int i = 0; i < 10; i++) {
        int id = tid + i * 256;
        if (id < 2400) {
            int ph = id / 24, q = id % 24;
            int hy = ph / 10, hx = ph % 10;
            int gy = y0 + hy, gx = x0 + hx;
            uint4 v = make_uint4(0u, 0u, 0u, 0u);
            if (gy >= 0 && gy < IMGHW && gx >= 0 && gx < IMGHW)
                v = *(const uint4*)(ip + (size_t)(gy * IMGHW + gx) * CDIM + q * 8);
            *(uint4*)(halo + ph * 192 + q * 8) = v;
        }
    }
    __syncthreads();

    #pragma unroll 1
    for (int pi = 0; pi < 8; pi++) {
        int t = wid * 8 + pi;
        int iy = t >> 3, ix = t & 7;
        const __nv_bfloat162* hp =
            (const __nv_bfloat162*)(halo + (iy * 10 + ix) * 192);
        float2 acc[3];
        float s1 = 0.f, s2 = 0.f;
        #pragma unroll
        for (int j = 0; j < 3; j++) {
            int cp = j * 32 + lane;
            float2 a = sb2[cp];
            #pragma unroll
            for (int tap = 0; tap < 9; tap++) {
                int ky = tap / 3, kx = tap % 3;
                __nv_bfloat162 v = hp[(ky * 10 + kx) * 96 + cp];
                float2 wv = swt[tap][cp];
                a.x = fmaf(__bfloat162float(v.x), wv.x, a.x);
                a.y = fmaf(__bfloat162float(v.y), wv.y, a.y);
            }
            acc[j] = a;
            s1 += a.x + a.y;
            s2 = fmaf(a.x, a.x, fmaf(a.y, a.y, s2));
        }
        #pragma unroll
        for (int o = 16; o > 0; o >>= 1) {
            s1 += __shfl_xor_sync(0xFFFFFFFFu, s1, o);
            s2 += __shfl_xor_sync(0xFFFFFFFFu, s2, o);
        }
        float mu = s1 * (1.0f / 192.0f);
        float var = s2 * (1.0f / 192.0f) - mu * mu;
        float rsd = rsqrtf(var + 1e-6f);
        __nv_bfloat16* op = pb + ((size_t)win * 64 + t) * 192;
        #pragma unroll
        for (int j = 0; j < 3; j++) {
            int cp = j * 32 + lane;
            float2 g = sg2[cp], bt = sbt2[cp];
            float v0 = fmaf((acc[j].x - mu) * rsd, g.x, bt.x);
            float v1 = fmaf((acc[j].y - mu) * rsd, g.y, bt.y);
            __nv_bfloat162 h2 = __floats2bfloat162_rn(v0, v1);
            *(uint32_t*)(op + 2 * cp) = *(uint32_t*)&h2;
        }
    }
}

// ---------------- merged weight prep + loss zero ----------------
__global__ void __launch_bounds__(256)
prep_kernel(const float* __restrict__ w_pre1, __nv_bfloat16* __restrict__ wtpre,
            const float* __restrict__ w_qkv,  __nv_bfloat16* __restrict__ wtq,
            const float* __restrict__ w_g1,   uint8_t* __restrict__ wg1f8,
            const float* __restrict__ w_g2,   uint8_t* __restrict__ wg2f8,
            const float* __restrict__ w_proj, uint8_t* __restrict__ wpjf8,
            const float* __restrict__ w_rec,  uint8_t* __restrict__ wrcf8,
            double* __restrict__ loss)
{
    int i = blockIdx.x * 256 + threadIdx.x;
    if (i == 0) *loss = 0.0;
    if (i < 36864) {
        wtpre[i] = __float2bfloat16(w_pre1[i]);
        return;
    }
    i -= 36864;
    if (i < 110592) {
        int k = i / 576, n = i % 576;
        wtq[n * 192 + k] = __float2bfloat16(w_qkv[i]);
        return;
    }
    i -= 110592;
    if (i < 147456) {
        int k = i / 768, n = i % 768;
        wg1f8[n * 192 + k] = (uint8_t)(to_e4m3x2(w_g1[i] * SCL_W, 0.f) & 0xFF);
        return;
    }
    i -= 147456;
    if (i < 147456) {
        int k = i / 192, n = i % 192;
        wg2f8[n * 768 + k] = (uint8_t)(to_e4m3x2(w_g2[i] * SCL_W, 0.f) & 0xFF);
        return;
    }
    i -= 147456;
    if (i < 36864) {
        int k = i / 192, n = i % 192;
        wpjf8[n * 192 + k] = (uint8_t)(to_e4m3x2(w_proj[i] * SCL_W, 0.f) & 0xFF);
        return;
    }
    i -= 36864;
    {
        int k = i / 192, n = i % 192;
        wrcf8[n * 192 + k] = (uint8_t)(to_e4m3x2(w_rec[i] * SCL_W, 0.f) & 0xFF);
    }
}

__global__ void finalize_loss_kernel(const double* l, float* out, size_t pos)
{
    out[pos] = (float)(l[0] * (0.1 / RECON_DENOM));
}

// ---------------- launch ----------------
extern "C" void kernel_launch(void* const* d_in, const int* in_sizes, int n_in,
                              void* d_out, int out_size)
{
    const float* x      = (const float*)d_in[0];
    const float* w_pre1 = (const float*)d_in[1];
    const float* b_pre1 = (const float*)d_in[2];
    const float* w_dw   = (const float*)d_in[3];
    const float* b_dw   = (const float*)d_in[4];
    const float* ln_g   = (const float*)d_in[5];
    const float* ln_b   = (const float*)d_in[6];
    const float* w_qkv  = (const float*)d_in[7];
    const float* b_qkv  = (const float*)d_in[8];
    const float* w_proj = (const float*)d_in[9];
    const float* b_proj = (const float*)d_in[10];
    const float* w_g1   = (const float*)d_in[11];
    const float* b_g1   = (const float*)d_in[12];
    const float* w_g2   = (const float*)d_in[13];
    const float* b_g2   = (const float*)d_in[14];
    const float* w_rec  = (const float*)d_in[15];
    const float* b_rec  = (const float*)d_in[16];
    float* out = (float*)d_out;

    double* loss;
    __nv_bfloat16 *attnb, *pb, *f1b;
    uint8_t *vf8, *hf8, *wg1f8, *wg2f8, *wpjf8, *wrcf8;
    __nv_bfloat16 *wtpre, *wtq;
    cudaGetSymbolAddress((void**)&attnb, g_attnb);
    cudaGetSymbolAddress((void**)&pb,    g_pb);
    cudaGetSymbolAddress((void**)&f1b,   g_f1b);
    cudaGetSymbolAddress((void**)&vf8,   g_vf8);
    cudaGetSymbolAddress((void**)&hf8,   g_hf8);
    cudaGetSymbolAddress((void**)&wtpre, g_wt_pre);
    cudaGetSymbolAddress((void**)&wtq,   g_wt_qkv);
    cudaGetSymbolAddress((void**)&wg1f8, g_wt_g1f8);
    cudaGetSymbolAddress((void**)&wg2f8, g_wt_g2f8);
    cudaGetSymbolAddress((void**)&wpjf8, g_wt_pjf8);
    cudaGetSymbolAddress((void**)&wrcf8, g_wt_rcf8);
    cudaGetSymbolAddress((void**)&loss,  g_lossd);

    __nv_bfloat16* xt = pb;     // xT dead before pb written (by dwconv_ln)

    cudaFuncSetAttribute(tail_kernel,
                         cudaFuncAttributeMaxDynamicSharedMemorySize, TAIL_SMEM);
    cudaFuncSetAttribute(qkv_attn_kernel,
                         cudaFuncAttributeMaxDynamicSharedMemorySize, QA_SMEM);
    cudaFuncSetAttribute(dwconv_ln_kernel,
                         cudaFuncAttributeMaxDynamicSharedMemorySize, DW_SMEM);

    // 0) weight prep + loss zero
    prep_kernel<<<2016, 256>>>(w_pre1, wtpre, w_qkv, wtq, w_g1, wg1f8,
                               w_g2, wg2f8, w_proj, wpjf8, w_rec, wrcf8, loss);

    // 1) x -> NHWC bf16
    transpose_x_kernel<<<dim3(HW / 32, CDIM / 32, BATCH), 256>>>(x, xt);

    // 2) 1x1 conv as HMMA GEMM
    hmma_gemm<<<dim3(2, NTOK / 128), 256>>>(xt, 192, wtpre, 192, b_pre1, f1b, 192);

    // 3) tiled depthwise 3x3 + LN + window partition -> pb (bf16)
    dwconv_ln_kernel<<<NWIN, 256, DW_SMEM>>>(f1b, w_dw, b_dw, ln_g, ln_b, pb);

    // 4+5) fused qkv GEMM + attention -> attnb, vf8
    qkv_attn_kernel<<<NWIN, 768, QA_SMEM>>>(pb, wtq, b_qkv, vf8, attnb);

    // 6) h = gelu(v @ w_g1 + b_g1)  -- FP8 GEMM
    fp8_gemm_gelu<<<dim3(8, NTOK / 128), 256>>>(
        vf8, 192, wg1f8, 192, b_g1, hf8, 768);

    // 7-10) fused tail (all-FP8 GEMM stages)
    tail_kernel<<<NWIN, 256, TAIL_SMEM>>>(
        hf8, wg2f8, b_g2, attnb, wpjf8, b_proj, wrcf8, b_rec, pb, x, out, loss);

    // 11) loss scalar
    if ((size_t)out_size > OUT_MAIN)
        finalize_loss_kernel<<<1, 1>>>(loss, out, (size_t)out_size - 1);
}

// round 17
// speedup vs baseline: 1.1352x; 1.0553x over previous
#include <cuda_runtime.h>
#include <cuda_bf16.h>
#include <math.h>
#include <stdint.h>

// ---------------- problem constants ----------------
#define CDIM   192
#define IMGHW  224
#define HW     (IMGHW*IMGHW)          // 50176
#define BATCH  4
#define HWC    ((size_t)CDIM*HW)
#define NWIN   3136
#define NTOK   200704                 // NWIN * 64 == BATCH*HW
#define OUT_MAIN ((size_t)BATCH*HWC)  // 38,535,168
#define RECON_DENOM 38535168.0

// fp8 scaling
#define SCL_A 8.0f                     // p, v, h activations
#define SCL_M 64.0f                    // m, fused activations
#define SCL_W 16.0f                    // weights
#define SCL_INV  (1.0f / (SCL_A * SCL_W))   // 1/128
#define SCL_INV2 (1.0f / (SCL_M * SCL_W))   // 1/1024

// ---------------- scratch (device globals) ----------------
__device__ __align__(16) __nv_bfloat16 g_attnb[(size_t)NTOK*192];
__device__ __align__(16) __nv_bfloat16 g_pb   [(size_t)NTOK*192];  // xT first, then pb
__device__ __align__(16) __nv_bfloat16 g_f1b  [(size_t)NTOK*192];  // conv1x1 out
__device__ __align__(16) uint8_t g_pf8 [(size_t)NTOK*192];         // p * 8, e4m3
__device__ __align__(16) uint8_t g_vf8 [(size_t)NTOK*192];         // v * 8, e4m3
__device__ __align__(16) uint8_t g_hf8 [(size_t)NTOK*768];         // h * 8, e4m3
__device__ __align__(16) __nv_bfloat16 g_wt_pre [192*192];
__device__ __align__(16) uint8_t g_wt_qkf8 [576*192];              // w_qkv^T * 16
__device__ __align__(16) uint8_t g_wt_g1f8 [768*192];              // w_g1^T * 16
__device__ __align__(16) uint8_t g_wt_g2f8 [192*768];              // w_g2^T * 16
__device__ __align__(16) uint8_t g_wt_pjf8 [192*192];              // w_proj^T * 16
__device__ __align__(16) uint8_t g_wt_rcf8 [192*192];              // w_rec^T * 16
__device__ double g_lossd[1];

// ---------------- HMMA / FP8 MMA / ldmatrix / cp.async helpers ------------
__device__ __forceinline__ void mma_bf16(float c[4],
    uint32_t a0, uint32_t a1, uint32_t a2, uint32_t a3,
    uint32_t b0, uint32_t b1)
{
    asm volatile(
        "mma.sync.aligned.m16n8k16.row.col.f32.bf16.bf16.f32 "
        "{%0,%1,%2,%3}, {%4,%5,%6,%7}, {%8,%9}, {%0,%1,%2,%3};"
        : "+f"(c[0]), "+f"(c[1]), "+f"(c[2]), "+f"(c[3])
        : "r"(a0), "r"(a1), "r"(a2), "r"(a3), "r"(b0), "r"(b1));
}
__device__ __forceinline__ void mma_fp8(float c[4],
    uint32_t a0, uint32_t a1, uint32_t a2, uint32_t a3,
    uint32_t b0, uint32_t b1)
{
    asm volatile(
        "mma.sync.aligned.m16n8k32.row.col.f32.e4m3.e4m3.f32 "
        "{%0,%1,%2,%3}, {%4,%5,%6,%7}, {%8,%9}, {%0,%1,%2,%3};"
        : "+f"(c[0]), "+f"(c[1]), "+f"(c[2]), "+f"(c[3])
        : "r"(a0), "r"(a1), "r"(a2), "r"(a3), "r"(b0), "r"(b1));
}
__device__ __forceinline__ void ldsm4(uint32_t& r0, uint32_t& r1,
                                      uint32_t& r2, uint32_t& r3,
                                      const __nv_bfloat16* p)
{
    uint32_t a = (uint32_t)__cvta_generic_to_shared(p);
    asm volatile("ldmatrix.sync.aligned.m8n8.x4.shared.b16 {%0,%1,%2,%3}, [%4];"
        : "=r"(r0), "=r"(r1), "=r"(r2), "=r"(r3) : "r"(a));
}
__device__ __forceinline__ void cp_async16(__nv_bfloat16* dst, const void* src)
{
    uint32_t d = (uint32_t)__cvta_generic_to_shared(dst);
    asm volatile("cp.async.cg.shared.global [%0], [%1], 16;" :: "r"(d), "l"(src));
}
#define CP_COMMIT() asm volatile("cp.async.commit_group;" ::: "memory")
#define CP_WAIT1()  asm volatile("cp.async.wait_group 1;" ::: "memory")

__device__ __forceinline__ uint16_t to_e4m3x2(float lo, float hi)
{
    uint16_t r;
    asm("cvt.rn.satfinite.e4m3x2.f32 %0, %1, %2;" : "=h"(r) : "f"(hi), "f"(lo));
    return r;
}

// ---------------- bf16 HMMA GEMM (conv1x1) ----------------
__global__ void __launch_bounds__(256)
hmma_gemm(const __nv_bfloat16* __restrict__ A, int lda,
          const __nv_bfloat16* __restrict__ BT, int K,
          const float* __restrict__ bias,
          __nv_bfloat16* __restrict__ Cb, int ldc)
{
    __shared__ __align__(16) __nv_bfloat16 sA[3][128][40];
    __shared__ __align__(16) __nv_bfloat16 sB[3][96][40];

    const int tid = threadIdx.x;
    const int lane = tid & 31, wid = tid >> 5;
    const int wm = wid & 3, wn = wid >> 2;

    const __nv_bfloat16* Ab = A + (size_t)(blockIdx.y * 128) * lda;
    const __nv_bfloat16* Bb = BT + (size_t)(blockIdx.x * 96) * K;

    float acc[2][6][4] = {};
    const int nk = K >> 5;

    const int lr = tid >> 2, lq = tid & 3;
    #define ISSUE_CHUNK(buf, k0) do {                                         \
        cp_async16(&sA[buf][lr][lq * 8],                                      \
                   Ab + (size_t)lr * lda + (k0) + lq * 8);                    \
        cp_async16(&sA[buf][lr + 64][lq * 8],                                 \
                   Ab + (size_t)(lr + 64) * lda + (k0) + lq * 8);             \
        cp_async16(&sB[buf][lr][lq * 8],                                      \
                   Bb + (size_t)lr * K + (k0) + lq * 8);                      \
        if (tid < 128)                                                        \
            cp_async16(&sB[buf][lr + 64][lq * 8],                             \
                       Bb + (size_t)(lr + 64) * K + (k0) + lq * 8);           \
    } while (0)

    ISSUE_CHUNK(0, 0);
    CP_COMMIT();

    for (int kc = 0; kc < nk; kc++) {
        if (kc + 1 < nk) ISSUE_CHUNK((kc + 1) % 3, (kc + 1) * 32);
        CP_COMMIT();
        CP_WAIT1();
        __syncthreads();
        const int b = kc % 3;

        #pragma unroll
        for (int ks = 0; ks < 2; ks++) {
            const int kb = ks * 16;
            uint32_t af[2][4];
            #pragma unroll
            for (int mi = 0; mi < 2; mi++)
                ldsm4(af[mi][0], af[mi][1], af[mi][2], af[mi][3],
                      &sA[b][wm * 32 + mi * 16 + (lane & 15)]
                           [kb + ((lane >> 4) << 3)]);
            uint32_t bfr[6][2];
            #pragma unroll
            for (int nj = 0; nj < 3; nj++)
                ldsm4(bfr[2*nj][0], bfr[2*nj][1], bfr[2*nj+1][0], bfr[2*nj+1][1],
                      &sB[b][wn * 48 + nj * 16 + (lane & 7) + ((lane >> 4) << 3)]
                           [kb + (((lane >> 3) & 1) << 3)]);
            #pragma unroll
            for (int ni = 0; ni < 6; ni++)
                #pragma unroll
                for (int mi = 0; mi < 2; mi++)
                    mma_bf16(acc[mi][ni], af[mi][0], af[mi][1], af[mi][2],
                             af[mi][3], bfr[ni][0], bfr[ni][1]);
        }
    }
    #undef ISSUE_CHUNK

    #pragma unroll
    for (int mi = 0; mi < 2; mi++) {
        #pragma unroll
        for (int ni = 0; ni < 6; ni++) {
            int r0 = blockIdx.y * 128 + wm * 32 + mi * 16 + (lane >> 2);
            int n0 = blockIdx.x * 96 + wn * 48 + ni * 8 + (lane & 3) * 2;
            float b0 = bias[n0], b1 = bias[n0 + 1];
            #pragma unroll
            for (int h = 0; h < 2; h++) {
                int r = r0 + h * 8;
                float v0 = acc[mi][ni][2 * h] + b0;
                float v1 = acc[mi][ni][2 * h + 1] + b1;
                __nv_bfloat162 h2 = __floats2bfloat162_rn(v0, v1);
                *(uint32_t*)(Cb + (size_t)r * ldc + n0) = *(uint32_t*)&h2;
            }
        }
    }
}

// ---------------- fused qkv GEMM (FP8) + attention ----------------
// smem units: sq 37376 | sA8 6656 (64x104) | sB8 2x19968 (192x104) | vt 13824
#define QA_SMEM ((37376 + 6656 + 2*19968 + 13824) * 2)   // 195584 B

__global__ void __launch_bounds__(768)
qkv_attn_kernel(const uint8_t* __restrict__ pf8,
                const uint8_t* __restrict__ wqkf8,
                const float* __restrict__ bq,
                uint8_t* __restrict__ vf8,
                __nv_bfloat16* __restrict__ attnb)
{
    extern __shared__ __align__(16) __nv_bfloat16 sm[];
    __nv_bfloat16* sq  = sm;                  // 64 x 584 (qkv result)
    __nv_bfloat16* sA8 = sm + 37376;          // 64 x 104 units (fp8 A)
    __nv_bfloat16* sB8 = sm + 44032;          // 2 x 192 x 104 units (fp8 B)
    __nv_bfloat16* vt  = sm + 83968;          // 192 x 72

    const int tid = threadIdx.x, lane = tid & 31, wid = tid >> 5;
    const int win = blockIdx.x;

    // load p fp8 tile (64 x 192B) with plain stores; first sync orders them
    {
        const uint8_t* Ap = pf8 + (size_t)win * 64 * 192;
        int r = tid / 12, q = tid % 12;
        *(uint4*)((uint8_t*)sA8 + r * 208 + q * 16) =
            *(const uint4*)(Ap + (size_t)r * 192 + q * 16);
    }

    // B issue: one pass = 192 rows x 192B? no: per pass rows n in [p*192,(p+1)*192), K=192B
    #define QA_ISSUEB8(buf, p) do {                                           \
        _Pragma("unroll")                                                     \
        for (int i = 0; i < 3; i++) {                                         \
            int id = tid + i * 768;                                           \
            int r = id / 12, q = id % 12;                                     \
            cp_async16(sB8 + (buf) * 19968 + r * 104 + q * 8,                 \
                       wqkf8 + ((size_t)(p) * 192 + r) * 192 + q * 16);       \
        }                                                                     \
    } while (0)

    const int wm = wid & 3, wn = wid >> 2;   // 4M x 6N

    QA_ISSUEB8(0, 0);
    CP_COMMIT();

    #pragma unroll 1
    for (int pass = 0; pass < 3; pass++) {
        if (pass < 2) QA_ISSUEB8((pass + 1) & 1, pass + 1);
        CP_COMMIT();
        CP_WAIT1();
        __syncthreads();
        const __nv_bfloat16* bbuf = sB8 + (pass & 1) * 19968;

        float acc[4][4] = {};
        #pragma unroll
        for (int ks2 = 0; ks2 < 6; ks2++) {
            const int kb = ks2 * 16;
            uint32_t a0, a1, a2, a3;
            ldsm4(a0, a1, a2, a3,
                  sA8 + (wm * 16 + (lane & 15)) * 104 + kb + ((lane >> 4) << 3));
            uint32_t bfr[4][2];
            #pragma unroll
            for (int nj = 0; nj < 2; nj++)
                ldsm4(bfr[2*nj][0], bfr[2*nj][1], bfr[2*nj+1][0], bfr[2*nj+1][1],
                      bbuf + (wn * 32 + nj * 16 + (lane & 7) + ((lane >> 4) << 3)) * 104
                           + kb + (((lane >> 3) & 1) << 3));
            #pragma unroll
            for (int ni = 0; ni < 4; ni++)
                mma_fp8(acc[ni], a0, a1, a2, a3, bfr[ni][0], bfr[ni][1]);
        }
        // epilogue -> sq (and vf8 for pass 2); per-warp regions disjoint
        #pragma unroll
        for (int ni = 0; ni < 4; ni++) {
            int n0 = pass * 192 + wn * 32 + ni * 8 + (lane & 3) * 2;
            float b0 = bq[n0], b1 = bq[n0 + 1];
            #pragma unroll
            for (int h = 0; h < 2; h++) {
                int row = wm * 16 + (lane >> 2) + h * 8;
                float v0 = acc[ni][2 * h]     * SCL_INV + b0;
                float v1 = acc[ni][2 * h + 1] * SCL_INV + b1;
                __nv_bfloat162 h2 = __floats2bfloat162_rn(v0, v1);
                *(uint32_t*)(sq + row * 584 + n0) = *(uint32_t*)&h2;
                if (pass == 2)
                    *(uint16_t*)(vf8 + ((size_t)win * 64 + row) * 192 + (n0 - 384)) =
                        to_e4m3x2(v0 * SCL_A, v1 * SCL_A);
            }
        }
    }
    #undef QA_ISSUEB8
    __syncthreads();

    #pragma unroll
    for (int i = 0; i < 16; i++) {
        int id = tid + i * 768;
        int t = id & 63, ch = id >> 6;
        vt[ch * 72 + t] = sq[t * 584 + 384 + ch];
    }
    __syncthreads();

    const int h = wid >> 2, q0 = (wid & 3) * 16;
    const int hc = h * 32;

    float sc[8][4] = {};
    #pragma unroll
    for (int ks = 0; ks < 2; ks++) {
        int kof = ks * 16 + (lane & 3) * 2;
        const __nv_bfloat16* qp = sq + (q0 + (lane >> 2)) * 584 + hc + kof;
        uint32_t a0 = *(const uint32_t*)qp;
        uint32_t a1 = *(const uint32_t*)(qp + 8 * 584);
        uint32_t a2 = *(const uint32_t*)(qp + 8);
        uint32_t a3 = *(const uint32_t*)(qp + 8 * 584 + 8);
        #pragma unroll
        for (int nt = 0; nt < 8; nt++) {
            const __nv_bfloat16* kp =
                sq + (nt * 8 + (lane >> 2)) * 584 + 192 + hc + kof;
            mma_bf16(sc[nt], a0, a1, a2, a3,
                     *(const uint32_t*)kp, *(const uint32_t*)(kp + 8));
        }
    }

    float mlo = -1e30f, mhi = -1e30f;
    #pragma unroll
    for (int nt = 0; nt < 8; nt++) {
        #pragma unroll
        for (int j = 0; j < 4; j++) sc[nt][j] *= 0.17677669529663687f;
        mlo = fmaxf(mlo, fmaxf(sc[nt][0], sc[nt][1]));
        mhi = fmaxf(mhi, fmaxf(sc[nt][2], sc[nt][3]));
    }
    mlo = fmaxf(mlo, __shfl_xor_sync(0xFFFFFFFFu, mlo, 1));
    mlo = fmaxf(mlo, __shfl_xor_sync(0xFFFFFFFFu, mlo, 2));
    mhi = fmaxf(mhi, __shfl_xor_sync(0xFFFFFFFFu, mhi, 1));
    mhi = fmaxf(mhi, __shfl_xor_sync(0xFFFFFFFFu, mhi, 2));
    float slo = 0.f, shi = 0.f;
    #pragma unroll
    for (int nt = 0; nt < 8; nt++) {
        sc[nt][0] = __expf(sc[nt][0] - mlo);
        sc[nt][1] = __expf(sc[nt][1] - mlo);
        sc[nt][2] = __expf(sc[nt][2] - mhi);
        sc[nt][3] = __expf(sc[nt][3] - mhi);
        slo += sc[nt][0] + sc[nt][1];
        shi += sc[nt][2] + sc[nt][3];
    }
    slo += __shfl_xor_sync(0xFFFFFFFFu, slo, 1);
    slo += __shfl_xor_sync(0xFFFFFFFFu, slo, 2);
    shi += __shfl_xor_sync(0xFFFFFFFFu, shi, 1);
    shi += __shfl_xor_sync(0xFFFFFFFFu, shi, 2);
    float ilo = 1.0f / slo, ihi = 1.0f / shi;

    float o[4][4] = {};
    #pragma unroll
    for (int ks = 0; ks < 4; ks++) {
        __nv_bfloat162 p0 = __floats2bfloat162_rn(sc[2*ks][0],   sc[2*ks][1]);
        __nv_bfloat162 p1 = __floats2bfloat162_rn(sc[2*ks][2],   sc[2*ks][3]);
        __nv_bfloat162 p2 = __floats2bfloat162_rn(sc[2*ks+1][0], sc[2*ks+1][1]);
        __nv_bfloat162 p3 = __floats2bfloat162_rn(sc[2*ks+1][2], sc[2*ks+1][3]);
        int kof = ks * 16 + (lane & 3) * 2;
        #pragma unroll
        for (int nt = 0; nt < 4; nt++) {
            const __nv_bfloat16* vp = vt + (hc + nt * 8 + (lane >> 2)) * 72 + kof;
            mma_bf16(o[nt], *(uint32_t*)&p0, *(uint32_t*)&p1,
                     *(uint32_t*)&p2, *(uint32_t*)&p3,
                     *(const uint32_t*)vp, *(const uint32_t*)(vp + 8));
        }
    }

    int rlo = q0 + (lane >> 2), col = (lane & 3) * 2;
    #pragma unroll
    for (int nt = 0; nt < 4; nt++) {
        size_t ci = ((size_t)win * 64 + rlo) * 192 + hc + nt * 8 + col;
        __nv_bfloat162 w0 = __floats2bfloat162_rn(o[nt][0] * ilo, o[nt][1] * ilo);
        *(uint32_t*)(attnb + ci) = *(uint32_t*)&w0;
        __nv_bfloat162 w1 = __floats2bfloat162_rn(o[nt][2] * ihi, o[nt][3] * ihi);
        *(uint32_t*)(attnb + ci + (size_t)8 * 192) = *(uint32_t*)&w1;
    }
}

// ---------------- FP8 GEMM with GELU (g1) ----------------
__global__ void __launch_bounds__(256)
fp8_gemm_gelu(const uint8_t* __restrict__ A, int ldaB,
              const uint8_t* __restrict__ BT, int Kb,
              const float* __restrict__ bias,
              uint8_t* __restrict__ Cf8, int ldcB)
{
    __shared__ __align__(16) __nv_bfloat16 sA[3][128][40];
    __shared__ __align__(16) __nv_bfloat16 sB[3][96][40];

    const int tid = threadIdx.x;
    const int lane = tid & 31, wid = tid >> 5;
    const int wm = wid & 3, wn = wid >> 2;

    const uint8_t* Ab = A + (size_t)(blockIdx.y * 128) * ldaB;
    const uint8_t* Bb = BT + (size_t)(blockIdx.x * 96) * Kb;

    float acc[2][6][4] = {};
    const int nk = Kb >> 6;

    const int lr = tid >> 2, lq = tid & 3;
    #define ISSUE_CHUNK8(buf, k0) do {                                        \
        cp_async16(&sA[buf][lr][lq * 8],                                      \
                   Ab + (size_t)lr * ldaB + (k0) + lq * 16);                  \
        cp_async16(&sA[buf][lr + 64][lq * 8],                                 \
                   Ab + (size_t)(lr + 64) * ldaB + (k0) + lq * 16);           \
        cp_async16(&sB[buf][lr][lq * 8],                                      \
                   Bb + (size_t)lr * Kb + (k0) + lq * 16);                    \
        if (tid < 128)                                                        \
            cp_async16(&sB[buf][lr + 64][lq * 8],                             \
                       Bb + (size_t)(lr + 64) * Kb + (k0) + lq * 16);         \
    } while (0)

    ISSUE_CHUNK8(0, 0);
    CP_COMMIT();

    for (int kc = 0; kc < nk; kc++) {
        if (kc + 1 < nk) ISSUE_CHUNK8((kc + 1) % 3, (kc + 1) * 64);
        CP_COMMIT();
        CP_WAIT1();
        __syncthreads();
        const int b = kc % 3;

        #pragma unroll
        for (int ks = 0; ks < 2; ks++) {
            const int kb = ks * 16;
            uint32_t af[2][4];
            #pragma unroll
            for (int mi = 0; mi < 2; mi++)
                ldsm4(af[mi][0], af[mi][1], af[mi][2], af[mi][3],
                      &sA[b][wm * 32 + mi * 16 + (lane & 15)]
                           [kb + ((lane >> 4) << 3)]);
            uint32_t bfr[6][2];
            #pragma unroll
            for (int nj = 0; nj < 3; nj++)
                ldsm4(bfr[2*nj][0], bfr[2*nj][1], bfr[2*nj+1][0], bfr[2*nj+1][1],
                      &sB[b][wn * 48 + nj * 16 + (lane & 7) + ((lane >> 4) << 3)]
                           [kb + (((lane >> 3) & 1) << 3)]);
            #pragma unroll
            for (int ni = 0; ni < 6; ni++)
                #pragma unroll
                for (int mi = 0; mi < 2; mi++)
                    mma_fp8(acc[mi][ni], af[mi][0], af[mi][1], af[mi][2],
                            af[mi][3], bfr[ni][0], bfr[ni][1]);
        }
    }
    #undef ISSUE_CHUNK8

    #pragma unroll
    for (int mi = 0; mi < 2; mi++) {
        #pragma unroll
        for (int ni = 0; ni < 6; ni++) {
            int r0 = blockIdx.y * 128 + wm * 32 + mi * 16 + (lane >> 2);
            int n0 = blockIdx.x * 96 + wn * 48 + ni * 8 + (lane & 3) * 2;
            float b0 = bias[n0], b1 = bias[n0 + 1];
            #pragma unroll
            for (int h = 0; h < 2; h++) {
                int r = r0 + h * 8;
                float v0 = acc[mi][ni][2 * h] * SCL_INV + b0;
                float v1 = acc[mi][ni][2 * h + 1] * SCL_INV + b1;
                v0 = 0.5f * v0 * (1.0f + erff(v0 * 0.70710678118654752f));
                v1 = 0.5f * v1 * (1.0f + erff(v1 * 0.70710678118654752f));
                *(uint16_t*)(Cf8 + (size_t)r * ldcB + n0) =
                    to_e4m3x2(v0 * SCL_A, v1 * SCL_A);
            }
        }
    }
}

// ---------------- fused tail kernel (fp8 all stages) ----------------------
__device__ __forceinline__ void tail_frag_mma(
    const __nv_bfloat16* __restrict__ As, int asr, int akb,
    const __nv_bfloat16* __restrict__ Bs, int bkb,
    int wm, int wn, int lane, float acc[2][6][4])
{
    uint32_t af[2][4];
    #pragma unroll
    for (int mi = 0; mi < 2; mi++)
        ldsm4(af[mi][0], af[mi][1], af[mi][2], af[mi][3],
              As + (wm * 32 + mi * 16 + (lane & 15)) * asr
                 + akb + ((lane >> 4) << 3));
    uint32_t bfr[6][2];
    #pragma unroll
    for (int nj = 0; nj < 3; nj++)
        ldsm4(bfr[2*nj][0], bfr[2*nj][1], bfr[2*nj+1][0], bfr[2*nj+1][1],
              Bs + (wn * 48 + nj * 16 + (lane & 7) + ((lane >> 4) << 3)) * 40
                 + bkb + (((lane >> 3) & 1) << 3));
    #pragma unroll
    for (int ni = 0; ni < 6; ni++)
        #pragma unroll
        for (int mi = 0; mi < 2; mi++)
            mma_fp8(acc[mi][ni], af[mi][0], af[mi][1], af[mi][2], af[mi][3],
                    bfr[ni][0], bfr[ni][1]);
}

// smem: sA 2*64*40u | sB 2*192*40u | ms8 64*208B | fs 64*200u | fs8 64*208B
#define TAIL_SMEM (10240 + 30720 + 13312 + 25600 + 13312)   // 93184 B

__global__ void __launch_bounds__(256)
tail_kernel(const uint8_t* __restrict__ hf8,
            const uint8_t* __restrict__ wg2f8, const float* __restrict__ bg2,
            const __nv_bfloat16* __restrict__ attnb,
            const uint8_t* __restrict__ wpjf8, const float* __restrict__ bproj,
            const uint8_t* __restrict__ wrcf8, const float* __restrict__ brec,
            const __nv_bfloat16* __restrict__ pb, const float* __restrict__ xin,
            float* __restrict__ out, double* __restrict__ lossAcc)
{
    extern __shared__ __align__(16) __nv_bfloat16 sm[];
    __nv_bfloat16* sA  = sm;                   // 2 * 2560 units
    __nv_bfloat16* sB  = sm + 5120;            // 2 * 7680 units
    uint8_t* ms8 = (uint8_t*)(sm + 20480);     // 64 x 208 B
    __nv_bfloat16* fs  = sm + 27136;           // 64 x 200 units
    uint8_t* fs8 = (uint8_t*)(sm + 39936);     // 64 x 208 B
    __shared__ float red[256];

    const int tid = threadIdx.x;
    const int lane = tid & 31, wid = tid >> 5;
    const int wm = wid & 1, wn = wid >> 1;
    const int win = blockIdx.x;
    const uint8_t* Ab8 = hf8 + (size_t)win * 64 * 768;

    const int lr = tid >> 2, lq = tid & 3;
    #define TK_ISSUEA8(buf, k0)                                               \
        cp_async16(sA + (buf) * 2560 + lr * 40 + lq * 8,                      \
                   Ab8 + (size_t)lr * 768 + (k0) + lq * 16)
    #define TK_ISSUEB8(buf, Bg, ldb, k0) do {                                 \
        _Pragma("unroll")                                                     \
        for (int i = 0; i < 3; i++) {                                         \
            int r = lr + i * 64;                                              \
            cp_async16(sB + (buf) * 7680 + r * 40 + lq * 8,                   \
                       (Bg) + (size_t)r * (ldb) + (k0) + lq * 16);            \
        }                                                                     \
    } while (0)

    // ---- stage 1 (FP8): m = (h @ W_g2^T + b_g2) * attn, 12 chunks of 64B
    float acc1[2][6][4] = {};
    TK_ISSUEA8(0, 0);
    TK_ISSUEB8(0, wg2f8, 768, 0);
    CP_COMMIT();
    #pragma unroll 1
    for (int kc = 0; kc < 12; kc++) {
        int b = kc & 1;
        if (kc < 11) { TK_ISSUEA8(b ^ 1, (kc + 1) * 64); TK_ISSUEB8(b ^ 1, wg2f8, 768, (kc + 1) * 64); }
        CP_COMMIT();
        CP_WAIT1();
        __syncthreads();
        #pragma unroll
        for (int ks = 0; ks < 2; ks++)
            tail_frag_mma(sA + b * 2560, 40, ks * 16, sB + b * 7680, ks * 16,
                          wm, wn, lane, acc1);
        __syncthreads();
    }
    #pragma unroll
    for (int mi = 0; mi < 2; mi++) {
        #pragma unroll
        for (int ni = 0; ni < 6; ni++) {
            int col = wn * 48 + ni * 8 + (lane & 3) * 2;
            float b0 = bg2[col], b1 = bg2[col + 1];
            #pragma unroll
            for (int h = 0; h < 2; h++) {
                int row = wm * 32 + mi * 16 + (lane >> 2) + h * 8;
                size_t ci = ((size_t)win * 64 + row) * 192 + col;
                __nv_bfloat162 av = *(const __nv_bfloat162*)(attnb + ci);
                float v0 = (acc1[mi][ni][2 * h] * SCL_INV + b0) * __bfloat162float(av.x);
                float v1 = (acc1[mi][ni][2 * h + 1] * SCL_INV + b1) * __bfloat162float(av.y);
                *(uint16_t*)(ms8 + row * 208 + col) =
                    to_e4m3x2(v0 * SCL_M, v1 * SCL_M);
            }
        }
    }
    __syncthreads();

    // ---- stage 2 (FP8): fused = m @ W_proj^T + b_proj, 3 chunks of 64B ----
    float acc2[2][6][4] = {};
    TK_ISSUEB8(0, wpjf8, 192, 0);
    CP_COMMIT();
    #pragma unroll 1
    for (int kc = 0; kc < 3; kc++) {
        int b = kc & 1;
        if (kc < 2) TK_ISSUEB8(b ^ 1, wpjf8, 192, (kc + 1) * 64);
        CP_COMMIT();
        CP_WAIT1();
        __syncthreads();
        #pragma unroll
        for (int ks = 0; ks < 2; ks++)
            tail_frag_mma((const __nv_bfloat16*)ms8, 104, kc * 32 + ks * 16,
                          sB + b * 7680, ks * 16, wm, wn, lane, acc2);
        __syncthreads();
    }
    #pragma unroll
    for (int mi = 0; mi < 2; mi++) {
        #pragma unroll
        for (int ni = 0; ni < 6; ni++) {
            int col = wn * 48 + ni * 8 + (lane & 3) * 2;
            float b0 = bproj[col], b1 = bproj[col + 1];
            #pragma unroll
            for (int h = 0; h < 2; h++) {
                int row = wm * 32 + mi * 16 + (lane >> 2) + h * 8;
                float v0 = acc2[mi][ni][2 * h]     * SCL_INV2 + b0;
                float v1 = acc2[mi][ni][2 * h + 1] * SCL_INV2 + b1;
                __nv_bfloat162 h2 = __floats2bfloat162_rn(v0, v1);
                *(uint32_t*)(fs + row * 200 + col) = *(uint32_t*)&h2;
                *(uint16_t*)(fs8 + row * 208 + col) =
                    to_e4m3x2(v0 * SCL_M, v1 * SCL_M);
            }
        }
    }
    __syncthreads();

    // ---- stage 3 (FP8): rec = fused @ W_rec^T + b_rec, L1 loss vs pb -----
    float acc3[2][6][4] = {};
    TK_ISSUEB8(0, wrcf8, 192, 0);
    CP_COMMIT();
    #pragma unroll 1
    for (int kc = 0; kc < 3; kc++) {
        int b = kc & 1;
        if (kc < 2) TK_ISSUEB8(b ^ 1, wrcf8, 192, (kc + 1) * 64);
        CP_COMMIT();
        CP_WAIT1();
        __syncthreads();
        #pragma unroll
        for (int ks = 0; ks < 2; ks++)
            tail_frag_mma((const __nv_bfloat16*)fs8, 104, kc * 32 + ks * 16,
                          sB + b * 7680, ks * 16, wm, wn, lane, acc3);
        __syncthreads();
    }
    float lsum = 0.f;
    #pragma unroll
    for (int mi = 0; mi < 2; mi++) {
        #pragma unroll
        for (int ni = 0; ni < 6; ni++) {
            int col = wn * 48 + ni * 8 + (lane & 3) * 2;
            float b0 = brec[col], b1 = brec[col + 1];
            #pragma unroll
            for (int h = 0; h < 2; h++) {
                int row = wm * 32 + mi * 16 + (lane >> 2) + h * 8;
                size_t ci = ((size_t)win * 64 + row) * 192 + col;
                __nv_bfloat162 pv = *(const __nv_bfloat162*)(pb + ci);
                lsum += fabsf(acc3[mi][ni][2 * h]     * SCL_INV2 + b0 - __bfloat162float(pv.x));
                lsum += fabsf(acc3[mi][ni][2 * h + 1] * SCL_INV2 + b1 - __bfloat162float(pv.y));
            }
        }
    }
    red[tid] = lsum;
    __syncthreads();
    #pragma unroll
    for (int s = 128; s > 0; s >>= 1) {
        if (tid < s) red[tid] += red[tid + s];
        __syncthreads();
    }
    if (tid == 0) atomicAdd(lossAcc, (double)red[0]);

    // ---- stage 4: window reverse + residual -> NCHW out ----
    int bb = win / 784;
    int wr = win % 784;
    int wy = wr / 28, wx = wr % 28;
    size_t base = (size_t)bb * HWC + (size_t)(wy * 8) * IMGHW + wx * 8;
    for (int idx = tid; idx < 64 * 192; idx += 256) {
        int c = idx >> 6, t = idx & 63;
        int iy = t >> 3, ix = t & 7;
        size_t o = base + (size_t)c * HW + iy * IMGHW + ix;
        out[o] = __bfloat162float(fs[t * 200 + c]) + xin[o];
    }
    #undef TK_ISSUEA8
    #undef TK_ISSUEB8
}

// ---------------- x transpose: NCHW fp32 -> NHWC bf16 ----------------
__global__ void __launch_bounds__(256)
transpose_x_kernel(const float* __restrict__ x, __nv_bfloat16* __restrict__ xt)
{
    __shared__ float tile[32][33];
    int s0 = blockIdx.x * 32, c0 = blockIdx.y * 32, b = blockIdx.z;
    int tx = threadIdx.x & 31, ty = threadIdx.x >> 5;
    const float* xp = x + (size_t)b * HWC;
    #pragma unroll
    for (int j = 0; j < 4; j++)
        tile[ty + 8 * j][tx] = xp[(size_t)(c0 + ty + 8 * j) * HW + s0 + tx];
    __syncthreads();
    __nv_bfloat16* op = xt + (size_t)b * HW * CDIM;
    #pragma unroll
    for (int j = 0; j < 4; j++)
        op[(size_t)(s0 + ty + 8 * j) * CDIM + c0 + tx] =
            __float2bfloat16(tile[tx][ty + 8 * j]);
}

// ---------------- tiled depthwise 3x3 + LN + window partition -------------
#define DW_SMEM (100 * 192 * 2)   // 38400 B

__global__ void __launch_bounds__(256)
dwconv_ln_kernel(const __nv_bfloat16* __restrict__ in,
                 const float* __restrict__ w, const float* __restrict__ bias,
                 const float* __restrict__ lng, const float* __restrict__ lnb,
                 __nv_bfloat16* __restrict__ pb, uint8_t* __restrict__ pf8)
{
    extern __shared__ __align__(16) __nv_bfloat16 halo[];   // [100][192]
    __shared__ float2 swt[9][96];          // [tap][chpair]
    __shared__ float2 sb2[96], sg2[96], sbt2[96];
    int tid = threadIdx.x, lane = tid & 31, wid = tid >> 5;
    int win = blockIdx.x;
    int b = win / 784, wr = win % 784, wy = wr / 28, wx = wr % 28;

    for (int i = tid; i < 1728; i += 256) {
        int c = i / 9, tap = i % 9;
        ((float*)&swt[tap][c >> 1])[c & 1] = w[i];
    }
    if (tid < 96) {
        sb2[tid]  = make_float2(bias[2*tid], bias[2*tid+1]);
        sg2[tid]  = make_float2(lng[2*tid],  lng[2*tid+1]);
        sbt2[tid] = make_float2(lnb[2*tid],  lnb[2*tid+1]);
    }

    const __nv_bfloat16* ip = in + (size_t)b * HW * CDIM;
    int y0 = wy * 8 - 1, x0 = wx * 8 - 1;
    #pragma unroll
    for (int i = 0; i < 10; i++) {
        int id = tid + i * 256;
        if (id < 2400) {
            int ph = id / 24, q = id % 24;
            int hy = ph / 10, hx = ph % 10;
            int gy = y0 + hy, gx = x0 + hx;
            uint4 v = make_uint4(0u, 0u, 0u, 0u);
            if (gy >= 0 && gy < IMGHW && gx >= 0 && gx < IMGHW)
                v = *(const uint4*)(ip + (size_t)(gy * IMGHW + gx) * CDIM + q * 8);
            *(uint4*)(halo + ph * 192 + q * 8) = v;
        }
    }
    __syncthreads();

    #pragma unroll 1
    for (int pi = 0; pi < 8; pi++) {
        int t = wid * 8 + pi;
        int iy = t >> 3, ix = t & 7;
        const __nv_bfloat162* hp =
            (const __nv_bfloat162*)(halo + (iy * 10 + ix) * 192);
        float2 acc[3];
        float s1 = 0.f, s2 = 0.f;
        #pragma unroll
        for (int j = 0; j < 3; j++) {
            int cp = j * 32 + lane;
            float2 a = sb2[cp];
            #pragma unroll
            for (int tap = 0; tap < 9; tap++) {
                int ky = tap / 3, kx = tap % 3;
                __nv_bfloat162 v = hp[(ky * 10 + kx) * 96 + cp];
                float2 wv = swt[tap][cp];
                a.x = fmaf(__bfloat162float(v.x), wv.x, a.x);
                a.y = fmaf(__bfloat162float(v.y), wv.y, a.y);
            }
            acc[j] = a;
            s1 += a.x + a.y;
            s2 = fmaf(a.x, a.x, fmaf(a.y, a.y, s2));
        }
        #pragma unroll
        for (int o = 16; o > 0; o >>= 1) {
            s1 += __shfl_xor_sync(0xFFFFFFFFu, s1, o);
            s2 += __shfl_xor_sync(0xFFFFFFFFu, s2, o);
        }
        float mu = s1 * (1.0f / 192.0f);
        float var = s2 * (1.0f / 192.0f) - mu * mu;
        float rsd = rsqrtf(var + 1e-6f);
        __nv_bfloat16* op = pb + ((size_t)win * 64 + t) * 192;
        uint8_t* op8 = pf8 + ((size_t)win * 64 + t) * 192;
        #pragma unroll
        for (int j = 0; j < 3; j++) {
            int cp = j * 32 + lane;
            float2 g = sg2[cp], bt = sbt2[cp];
            float v0 = fmaf((acc[j].x - mu) * rsd, g.x, bt.x);
            float v1 = fmaf((acc[j].y - mu) * rsd, g.y, bt.y);
            __nv_bfloat162 h2 = __floats2bfloat162_rn(v0, v1);
            *(uint32_t*)(op + 2 * cp) = *(uint32_t*)&h2;
            *(uint16_t*)(op8 + 2 * cp) = to_e4m3x2(v0 * SCL_A, v1 * SCL_A);
        }
    }
}

// ---------------- merged weight prep + loss zero ----------------
__global__ void __launch_bounds__(256)
prep_kernel(const float* __restrict__ w_pre1, __nv_bfloat16* __restrict__ wtpre,
            const float* __restrict__ w_qkv,  uint8_t* __restrict__ wqkf8,
            const float* __restrict__ w_g1,   uint8_t* __restrict__ wg1f8,
            const float* __restrict__ w_g2,   uint8_t* __restrict__ wg2f8,
            const float* __restrict__ w_proj, uint8_t* __restrict__ wpjf8,
            const float* __restrict__ w_rec,  uint8_t* __restrict__ wrcf8,
            double* __restrict__ loss)
{
    int i = blockIdx.x * 256 + threadIdx.x;
    if (i == 0) *loss = 0.0;
    if (i < 36864) {
        wtpre[i] = __float2bfloat16(w_pre1[i]);
        return;
    }
    i -= 36864;
    if (i < 110592) {
        int k = i / 576, n = i % 576;
        wqkf8[n * 192 + k] = (uint8_t)(to_e4m3x2(w_qkv[i] * SCL_W, 0.f) & 0xFF);
        return;
    }
    i -= 110592;
    if (i < 147456) {
        int k = i / 768, n = i % 768;
        wg1f8[n * 192 + k] = (uint8_t)(to_e4m3x2(w_g1[i] * SCL_W, 0.f) & 0xFF);
        return;
    }
    i -= 147456;
    if (i < 147456) {
        int k = i / 192, n = i % 192;
        wg2f8[n * 768 + k] = (uint8_t)(to_e4m3x2(w_g2[i] * SCL_W, 0.f) & 0xFF);
        return;
    }
    i -= 147456;
    if (i < 36864) {
        int k = i / 192, n = i % 192;
        wpjf8[n * 192 + k] = (uint8_t)(to_e4m3x2(w_proj[i] * SCL_W, 0.f) & 0xFF);
        return;
    }
    i -= 36864;
    {
        int k = i / 192, n = i % 192;
        wrcf8[n * 192 + k] = (uint8_t)(to_e4m3x2(w_rec[i] * SCL_W, 0.f) & 0xFF);
    }
}

__global__ void finalize_loss_kernel(const double* l, float* out, size_t pos)
{
    out[pos] = (float)(l[0] * (0.1 / RECON_DENOM));
}

// ---------------- launch ----------------
extern "C" void kernel_launch(void* const* d_in, const int* in_sizes, int n_in,
                              void* d_out, int out_size)
{
    const float* x      = (const float*)d_in[0];
    const float* w_pre1 = (const float*)d_in[1];
    const float* b_pre1 = (const float*)d_in[2];
    const float* w_dw   = (const float*)d_in[3];
    const float* b_dw   = (const float*)d_in[4];
    const float* ln_g   = (const float*)d_in[5];
    const float* ln_b   = (const float*)d_in[6];
    const float* w_qkv  = (const float*)d_in[7];
    const float* b_qkv  = (const float*)d_in[8];
    const float* w_proj = (const float*)d_in[9];
    const float* b_proj = (const float*)d_in[10];
    const float* w_g1   = (const float*)d_in[11];
    const float* b_g1   = (const float*)d_in[12];
    const float* w_g2   = (const float*)d_in[13];
    const float* b_g2   = (const float*)d_in[14];
    const float* w_rec  = (const float*)d_in[15];
    const float* b_rec  = (const float*)d_in[16];
    float* out = (float*)d_out;

    double* loss;
    __nv_bfloat16 *attnb, *pb, *f1b, *wtpre;
    uint8_t *pf8, *vf8, *hf8, *wqkf8, *wg1f8, *wg2f8, *wpjf8, *wrcf8;
    cudaGetSymbolAddress((void**)&attnb, g_attnb);
    cudaGetSymbolAddress((void**)&pb,    g_pb);
    cudaGetSymbolAddress((void**)&f1b,   g_f1b);
    cudaGetSymbolAddress((void**)&pf8,   g_pf8);
    cudaGetSymbolAddress((void**)&vf8,   g_vf8);
    cudaGetSymbolAddress((void**)&hf8,   g_hf8);
    cudaGetSymbolAddress((void**)&wtpre, g_wt_pre);
    cudaGetSymbolAddress((void**)&wqkf8, g_wt_qkf8);
    cudaGetSymbolAddress((void**)&wg1f8, g_wt_g1f8);
    cudaGetSymbolAddress((void**)&wg2f8, g_wt_g2f8);
    cudaGetSymbolAddress((void**)&wpjf8, g_wt_pjf8);
    cudaGetSymbolAddress((void**)&wrcf8, g_wt_rcf8);
    cudaGetSymbolAddress((void**)&loss,  g_lossd);

    __nv_bfloat16* xt = pb;     // xT dead before pb written (by dwconv_ln)

    cudaFuncSetAttribute(tail_kernel,
                         cudaFuncAttributeMaxDynamicSharedMemorySize, TAIL_SMEM);
    cudaFuncSetAttribute(qkv_attn_kernel,
                         cudaFuncAttributeMaxDynamicSharedMemorySize, QA_SMEM);
    cudaFuncSetAttribute(dwconv_ln_kernel,
                         cudaFuncAttributeMaxDynamicSharedMemorySize, DW_SMEM);

    // 0) weight prep + loss zero
    prep_kernel<<<2016, 256>>>(w_pre1, wtpre, w_qkv, wqkf8, w_g1, wg1f8,
                               w_g2, wg2f8, w_proj, wpjf8, w_rec, wrcf8, loss);

    // 1) x -> NHWC bf16
    transpose_x_kernel<<<dim3(HW / 32, CDIM / 32, BATCH), 256>>>(x, xt);

    // 2) 1x1 conv as HMMA GEMM
    hmma_gemm<<<dim3(2, NTOK / 128), 256>>>(xt, 192, wtpre, 192, b_pre1, f1b, 192);

    // 3) tiled depthwise 3x3 + LN + window partition -> pb (bf16) + pf8
    dwconv_ln_kernel<<<NWIN, 256, DW_SMEM>>>(f1b, w_dw, b_dw, ln_g, ln_b, pb, pf8);

    // 4+5) fused qkv GEMM (fp8, pass-pipelined) + attention -> attnb, vf8
    qkv_attn_kernel<<<NWIN, 768, QA_SMEM>>>(pf8, wqkf8, b_qkv, vf8, attnb);

    // 6) h = gelu(v @ w_g1 + b_g1)  -- FP8 GEMM
    fp8_gemm_gelu<<<dim3(8, NTOK / 128), 256>>>(
        vf8, 192, wg1f8, 192, b_g1, hf8, 768);

    // 7-10) fused tail (all-FP8 GEMM stages)
    tail_kernel<<<NWIN, 256, TAIL_SMEM>>>(
        hf8, wg2f8, b_g2, attnb, wpjf8, b_proj, wrcf8, b_rec, pb, x, out, loss);

    // 11) loss scalar
    if ((size_t)out_size > OUT_MAIN)
        finalize_loss_kernel<<<1, 1>>>(loss, out, (size_t)out_size - 1);
}